// round 11
// baseline (speedup 1.0000x reference)
#include <cuda_runtime.h>
#include <math.h>
#include <stdint.h>

#define TT 200
#define BB 64
#define SS 8
#define DD 128
#define RR 512
#define ZZ 256
#define HH 1024
#define BSZ (BB*SS)            /* 512 rows per step */
#define DT_C 0.05f
#define SQRT_DT_C 0.223606797749979f
#define LOG2PI_C 1.8378770664093453f

#define KLD_PARTS  (800*4)
#define RECON_PARTS (800*2)

#define SCAN_BLOCKS 128
#define SCAN_THREADS 256

// ---------------- device scratch (static, allocation-free) ----------------
__device__ float g_hprior[TT*BB*HH];        // h@drift_w1[:R] + b1
__device__ float g_hpost [TT*BB*HH];        // hpos@drift_w1[:R] + b1
__device__ float g_ppart [TT*BB*HH];        // h@p_w1[:R] + p_b1
__device__ float g_dtmp  [TT*BB*HH];        // relu(h@diff_w1+b1)
__device__ float g_diff  [TT*BB*ZZ];        // exp(diff MLP)
__device__ float g_Mt    [TT*BB];
__device__ float g_states[(TT+1)*BSZ*ZZ];   // z trajectory (normalized)
__device__ float g_zw    [TT*BSZ*HH];       // z_t @ drift_w1[R:]
__device__ float g_post  [TT*BSZ*ZZ];       // posterior drift
__device__ float g_A3    [TT*BSZ*HH];       // decoder hidden
__device__ float g_part  [4*BSZ*ZZ];        // split-K partials for scan
__device__ float g_kld_part[KLD_PARTS];
__device__ float g_recon_part[RECON_PARTS];
__device__ unsigned g_cnt[32*32];           // spread barrier counters (128B apart)

// ---------------- tf32 / async helpers ----------------
__device__ __forceinline__ uint32_t f2tf(float f)
{
    uint32_t u;
    asm("cvt.rna.tf32.f32 %0, %1;" : "=r"(u) : "f"(f));
    return u;
}

__device__ __forceinline__ uint32_t f2tf_u(uint32_t raw)
{
    return f2tf(__uint_as_float(raw));
}

__device__ __forceinline__ void mma8(float* c,
    uint32_t a0, uint32_t a1, uint32_t a2, uint32_t a3,
    uint32_t b0, uint32_t b1)
{
    asm("mma.sync.aligned.m16n8k8.row.col.f32.tf32.tf32.f32 "
        "{%0,%1,%2,%3},{%4,%5,%6,%7},{%8,%9},{%0,%1,%2,%3};"
        : "+f"(c[0]), "+f"(c[1]), "+f"(c[2]), "+f"(c[3])
        : "r"(a0), "r"(a1), "r"(a2), "r"(a3), "r"(b0), "r"(b1));
}

__device__ __forceinline__ void cp16(uint32_t smem_dst, const void* gsrc)
{
    asm volatile("cp.async.cg.shared.global [%0], [%1], 16;\n"
                 :: "r"(smem_dst), "l"(gsrc));
}
#define CP_COMMIT() asm volatile("cp.async.commit_group;\n" ::: "memory")
#define CP_WAIT1()  asm volatile("cp.async.wait_group 1;\n" ::: "memory")
#define CP_WAIT0()  asm volatile("cp.async.wait_group 0;\n" ::: "memory")

// ---------------- generic 128x64 tf32 GEMM with fused pro/epilogues ------
#define PRO_PLAIN 0
#define PRO_ADDRELU 1      // A := relu(A + aux[(m>>3)*H + k])
#define EPI_STORE 0        // C = acc (+bias)
#define EPI_RELU  1
#define EPI_EXP   2
#define EPI_BCASTRELU 3    // C = relu(acc + aux[(m>>3)*H + n])
#define EPI_KLD   4        // reduce ((0.1 tanh(acc+b)-post)/diff)^2
#define EPI_RECON 5        // reduce 0.5(log2pi+(X-(acc+b))^2)*Mt

template<int PRO, int EPI>
__global__ void __launch_bounds__(256) gemm_t(
    const float* __restrict__ A, int lda,
    const float* __restrict__ Bm, int ldb,
    float* __restrict__ C, int ldc, int K,
    const float* __restrict__ bias,
    const float* __restrict__ aux,
    const float* __restrict__ aux2,
    const float* __restrict__ aux3,
    float* __restrict__ part)
{
    constexpr int AW = 36;            // A smem row stride (words), %32=4
    constexpr int BW = 72;            // B smem row stride (words), %32=8
    constexpr int ASZ = 128 * AW;
    constexpr int BSZW = 32 * BW;
    constexpr int NBUF = (PRO == PRO_PLAIN) ? 2 : 1;
    __shared__ uint32_t sm[NBUF * (ASZ + BSZW)];

    const int tid = threadIdx.x;
    const int m0 = blockIdx.y * 128, n0 = blockIdx.x * 64;
    const int wid = tid >> 5, lane = tid & 31;
    const int wm = (wid & 3) * 32;     // warp row offset (4 warps along m)
    const int wn = (wid >> 2) * 32;    // warp col offset (2 warps along n)
    const int qr = lane >> 2;          // 0..7
    const int qc = lane & 3;           // 0..3

    float acc[2][4][4];
#pragma unroll
    for (int h = 0; h < 2; h++)
#pragma unroll
        for (int j = 0; j < 4; j++)
#pragma unroll
            for (int c = 0; c < 4; c++) acc[h][j][c] = 0.f;

    if (PRO == PRO_PLAIN) {
        const uint32_t smb = (uint32_t)__cvta_generic_to_shared(sm);
        auto stage = [&](int k0, int b) {
#pragma unroll
            for (int i = 0; i < 4; i++) {            // A: 128 rows x 32 k
                int slot = tid + 256 * i;
                int row = slot >> 3, k4 = (slot & 7) << 2;
                cp16(smb + (uint32_t)(b * (ASZ + BSZW) + row * AW + k4) * 4,
                     &A[(size_t)(m0 + row) * lda + k0 + k4]);
            }
#pragma unroll
            for (int i = 0; i < 2; i++) {            // B: 32 rows x 64 n
                int slot = tid + 256 * i;
                int row = slot >> 4, n4 = (slot & 15) << 2;
                cp16(smb + (uint32_t)(b * (ASZ + BSZW) + ASZ + row * BW + n4) * 4,
                     &Bm[(size_t)(k0 + row) * ldb + n0 + n4]);
            }
            CP_COMMIT();
        };

        stage(0, 0);
        int buf = 0;
        for (int k0 = 0; k0 < K; k0 += 32) {
            if (k0 + 32 < K) stage(k0 + 32, buf ^ 1);
            if (k0 + 32 < K) { CP_WAIT1(); } else { CP_WAIT0(); }
            __syncthreads();
            const uint32_t* As = sm + buf * (ASZ + BSZW);
            const uint32_t* Bs = As + ASZ;
#pragma unroll
            for (int k8 = 0; k8 < 4; k8++) {
                const int kk = k8 * 8;
                uint32_t a00 = f2tf_u(As[(wm + qr     ) * AW + kk + qc]);
                uint32_t a01 = f2tf_u(As[(wm + qr + 8 ) * AW + kk + qc]);
                uint32_t a02 = f2tf_u(As[(wm + qr     ) * AW + kk + qc + 4]);
                uint32_t a03 = f2tf_u(As[(wm + qr + 8 ) * AW + kk + qc + 4]);
                uint32_t a10 = f2tf_u(As[(wm + qr + 16) * AW + kk + qc]);
                uint32_t a11 = f2tf_u(As[(wm + qr + 24) * AW + kk + qc]);
                uint32_t a12 = f2tf_u(As[(wm + qr + 16) * AW + kk + qc + 4]);
                uint32_t a13 = f2tf_u(As[(wm + qr + 24) * AW + kk + qc + 4]);
#pragma unroll
                for (int j = 0; j < 4; j++) {
                    const int cn = wn + j * 8 + qr;
                    uint32_t b0 = f2tf_u(Bs[(kk + qc    ) * BW + cn]);
                    uint32_t b1 = f2tf_u(Bs[(kk + qc + 4) * BW + cn]);
                    mma8(acc[0][j], a00, a01, a02, a03, b0, b1);
                    mma8(acc[1][j], a10, a11, a12, a13, b0, b1);
                }
            }
            __syncthreads();
            buf ^= 1;
        }
    } else {
        // synchronous staged path (PRO_ADDRELU)
        uint32_t* As = sm;
        uint32_t* Bs = sm + ASZ;
        const int arow = tid >> 1;
        const int ab   = (tid & 1) * 16;
        const int brow = tid >> 3;
        const int bn   = (tid & 7) * 8;
        for (int k0 = 0; k0 < K; k0 += 32) {
#pragma unroll
            for (int i = 0; i < 4; i++) {
                float4 av = *(const float4*)&A[(size_t)(m0 + arow) * lda + k0 + ab + 4*i];
                const float4 hv = *(const float4*)&aux[(size_t)((m0 + arow) >> 3) * HH + k0 + ab + 4*i];
                av.x = fmaxf(av.x + hv.x, 0.f); av.y = fmaxf(av.y + hv.y, 0.f);
                av.z = fmaxf(av.z + hv.z, 0.f); av.w = fmaxf(av.w + hv.w, 0.f);
                uint4 t;
                t.x = f2tf(av.x); t.y = f2tf(av.y); t.z = f2tf(av.z); t.w = f2tf(av.w);
                *(uint4*)&As[arow * AW + ab + 4*i] = t;
            }
#pragma unroll
            for (int i = 0; i < 2; i++) {
                float4 bv = *(const float4*)&Bm[(size_t)(k0 + brow) * ldb + n0 + bn + 4*i];
                uint4 t;
                t.x = f2tf(bv.x); t.y = f2tf(bv.y); t.z = f2tf(bv.z); t.w = f2tf(bv.w);
                *(uint4*)&Bs[brow * BW + bn + 4*i] = t;
            }
            __syncthreads();
#pragma unroll
            for (int k8 = 0; k8 < 4; k8++) {
                const int kk = k8 * 8;
                uint32_t a00 = As[(wm + qr     ) * AW + kk + qc];
                uint32_t a01 = As[(wm + qr + 8 ) * AW + kk + qc];
                uint32_t a02 = As[(wm + qr     ) * AW + kk + qc + 4];
                uint32_t a03 = As[(wm + qr + 8 ) * AW + kk + qc + 4];
                uint32_t a10 = As[(wm + qr + 16) * AW + kk + qc];
                uint32_t a11 = As[(wm + qr + 24) * AW + kk + qc];
                uint32_t a12 = As[(wm + qr + 16) * AW + kk + qc + 4];
                uint32_t a13 = As[(wm + qr + 24) * AW + kk + qc + 4];
#pragma unroll
                for (int j = 0; j < 4; j++) {
                    const int cn = wn + j * 8 + qr;
                    uint32_t b0 = Bs[(kk + qc    ) * BW + cn];
                    uint32_t b1 = Bs[(kk + qc + 4) * BW + cn];
                    mma8(acc[0][j], a00, a01, a02, a03, b0, b1);
                    mma8(acc[1][j], a10, a11, a12, a13, b0, b1);
                }
            }
            __syncthreads();
        }
    }

    const int mA = m0 + wm + qr;
    const int nB0 = n0 + wn + qc * 2;

    if (EPI <= 3) {
        const bool hasb = (bias != nullptr);
#pragma unroll
        for (int h = 0; h < 2; h++) {
#pragma unroll
            for (int j = 0; j < 4; j++) {
                const int n = nB0 + j * 8;
                const int r0 = mA + h * 16, r1 = r0 + 8;
                float v[4] = {acc[h][j][0], acc[h][j][1], acc[h][j][2], acc[h][j][3]};
                const int mm[4] = {r0, r0, r1, r1};
                const int nn[4] = {n, n + 1, n, n + 1};
#pragma unroll
                for (int c = 0; c < 4; c++) {
                    if (hasb) v[c] += bias[nn[c]];
                    if (EPI == EPI_RELU) v[c] = fmaxf(v[c], 0.f);
                    if (EPI == EPI_EXP)  v[c] = expf(v[c]);
                    if (EPI == EPI_BCASTRELU)
                        v[c] = fmaxf(v[c] + aux[(size_t)(mm[c] >> 3) * HH + nn[c]], 0.f);
                }
                *(float2*)&C[(size_t)r0 * ldc + n] = make_float2(v[0], v[1]);
                *(float2*)&C[(size_t)r1 * ldc + n] = make_float2(v[2], v[3]);
            }
        }
    } else {
        float s = 0.f;
#pragma unroll
        for (int h = 0; h < 2; h++) {
#pragma unroll
            for (int j = 0; j < 4; j++) {
                const int n = nB0 + j * 8;
                const int r0 = mA + h * 16, r1 = r0 + 8;
                const int mm[4] = {r0, r0, r1, r1};
                const int nn[4] = {n, n + 1, n, n + 1};
#pragma unroll
                for (int c = 0; c < 4; c++) {
                    float v = acc[h][j][c] + bias[nn[c]];
                    if (EPI == EPI_KLD) {
                        float pr = 0.1f * tanhf(v);
                        float e = (pr - aux2[(size_t)mm[c] * ZZ + nn[c]]) /
                                  aux3[(size_t)(mm[c] >> 3) * ZZ + nn[c]];
                        s += e * e;
                    } else { // EPI_RECON
                        float d = aux[(size_t)(mm[c] >> 3) * DD + nn[c]] - v;
                        float nll = 0.5f * (LOG2PI_C + d * d);
                        s += nll * aux2[mm[c] >> 3];
                    }
                }
            }
        }
        __shared__ float red[256];
        red[tid] = s;
        __syncthreads();
        for (int o = 128; o > 0; o >>= 1) {
            if (tid < o) red[tid] += red[tid + o];
            __syncthreads();
        }
        if (tid == 0) part[blockIdx.y * gridDim.x + blockIdx.x] = red[0];
    }
}

// ---------------- persistent scan kernel (tf32, 8 warps, 32x16 tiles) -----
#define SMEM_SCAN ((256*72*2 + 64*260) * 4)

__device__ __forceinline__ void gridbar(unsigned& tgt)
{
    tgt += SCAN_BLOCKS;
    __syncthreads();
    if (threadIdx.x == 0) {
        __threadfence();
        atomicAdd(&g_cnt[(blockIdx.x & 31) << 5], 1u);
    }
    if (threadIdx.x < 32) {
        unsigned s;
        do {
            s = *(volatile unsigned*)&g_cnt[threadIdx.x << 5];
#pragma unroll
            for (int o = 16; o > 0; o >>= 1)
                s += __shfl_xor_sync(0xffffffffu, s, o);
        } while (s < tgt);
        __threadfence();
    }
    __syncthreads();
}

__global__ void __launch_bounds__(SCAN_THREADS, 1) scan_kernel(
    const float* __restrict__ w1z,      // drift_w1 + RR*HH
    const float* __restrict__ w2,       // drift_w2
    const float* __restrict__ b2,       // drift_b2
    const float* __restrict__ noise)
{
    extern __shared__ uint32_t smu[];
    uint32_t* W1s = smu;                     // [256][72]
    uint32_t* W2s = smu + 256*72;            // [256][72]
    uint32_t* St  = smu + 2*256*72;          // [64][260]

    const int tid = threadIdx.x;
    const int bid = blockIdx.x;
    const int wid = tid >> 5, lane = tid & 31;
    const int qr = lane >> 2;   // 0..7
    const int qc = lane & 3;    // 0..3

    // phase A geometry: 8 m-tiles (64 rows) x 16 n-slices (64 cols of 1024)
    // 8 warps: 2 along m (32 rows each) x 4 along n (16 cols each)
    const int bmA = bid >> 4;          // 0..7
    const int bnA = bid & 15;          // 0..15
    const int wmA = (wid & 1) * 32;
    const int wnA = (wid >> 1) * 16;

    // phase B1 geometry: 8 m-tiles(64r) x 4 n-tiles(64c) x 4 k-chunks(256)
    const int kcB = bid & 3;
    const int moB = (bid >> 2) >> 2;
    const int noB = (bid >> 2) & 3;
    const int wrB = (wid & 1) * 32;
    const int wcB = (wid >> 1) * 16;

    for (int i = tid; i < 256*64; i += SCAN_THREADS) {
        int k = i >> 6, c = i & 63;
        W1s[k*72 + c] = f2tf(w1z[(size_t)k*HH + bnA*64 + c]);
        W2s[k*72 + c] = f2tf(w2[(size_t)(kcB*256 + k)*ZZ + noB*64 + c]);
    }
    __syncthreads();

    unsigned tgt = 0;

    for (int t = 0; t < TT; t++) {
        const float* z = g_states + (size_t)t*BSZ*ZZ;
        float* zwt = g_zw + (size_t)t*BSZ*HH;

        // ============ phase A: zw[t] = z_t @ w1z (tf32 mma) ============
        {
            for (int i = tid; i < 64*64; i += SCAN_THREADS) {
                int row = i >> 6, q = (i & 63) << 2;
                float4 f = *(const float4*)&z[(size_t)(bmA*64 + row)*ZZ + q];
                uint4 u;
                u.x = f2tf(f.x); u.y = f2tf(f.y); u.z = f2tf(f.z); u.w = f2tf(f.w);
                *(uint4*)&St[row*260 + q] = u;
            }
            __syncthreads();

            float acc[2][2][4];
#pragma unroll
            for (int h = 0; h < 2; h++)
#pragma unroll
                for (int j = 0; j < 2; j++)
#pragma unroll
                    for (int c = 0; c < 4; c++) acc[h][j][c] = 0.f;

#pragma unroll 4
            for (int kb = 0; kb < 32; kb++) {
                const int kk = kb * 8;
                uint32_t a00 = St[(wmA + qr     )*260 + kk + qc];
                uint32_t a01 = St[(wmA + qr + 8 )*260 + kk + qc];
                uint32_t a02 = St[(wmA + qr     )*260 + kk + qc + 4];
                uint32_t a03 = St[(wmA + qr + 8 )*260 + kk + qc + 4];
                uint32_t a10 = St[(wmA + qr + 16)*260 + kk + qc];
                uint32_t a11 = St[(wmA + qr + 24)*260 + kk + qc];
                uint32_t a12 = St[(wmA + qr + 16)*260 + kk + qc + 4];
                uint32_t a13 = St[(wmA + qr + 24)*260 + kk + qc + 4];
#pragma unroll
                for (int j = 0; j < 2; j++) {
                    const int n = wnA + j*8 + qr;
                    uint32_t b0 = W1s[(kk + qc    )*72 + n];
                    uint32_t b1 = W1s[(kk + qc + 4)*72 + n];
                    mma8(acc[0][j], a00, a01, a02, a03, b0, b1);
                    mma8(acc[1][j], a10, a11, a12, a13, b0, b1);
                }
            }
            const int mA = bmA*64 + wmA + qr;
#pragma unroll
            for (int h = 0; h < 2; h++) {
#pragma unroll
                for (int j = 0; j < 2; j++) {
                    const int n = bnA*64 + wnA + j*8 + qc*2;
                    const int r0 = mA + h*16;
                    *(float2*)&zwt[(size_t)r0*HH + n]     = make_float2(acc[h][j][0], acc[h][j][1]);
                    *(float2*)&zwt[(size_t)(r0+8)*HH + n] = make_float2(acc[h][j][2], acc[h][j][3]);
                }
            }
        }
        gridbar(tgt);

        // ============ phase B1: partial relu(zw+hpost)@W2 (tf32 mma) ============
        {
            const float* hp = g_hpost + (size_t)t*BB*HH;
            for (int i = tid; i < 64*64; i += SCAN_THREADS) {
                int row = i >> 6, q = (i & 63) << 2;
                int gk = kcB*256 + q;
                float4 f  = *(const float4*)&zwt[(size_t)(moB*64 + row)*HH + gk];
                float4 h4 = *(const float4*)&hp[(size_t)((moB*64 + row) >> 3)*HH + gk];
                uint4 u;
                u.x = f2tf(fmaxf(f.x + h4.x, 0.f));
                u.y = f2tf(fmaxf(f.y + h4.y, 0.f));
                u.z = f2tf(fmaxf(f.z + h4.z, 0.f));
                u.w = f2tf(fmaxf(f.w + h4.w, 0.f));
                *(uint4*)&St[row*260 + q] = u;
            }
            __syncthreads();

            float acc[2][2][4];
#pragma unroll
            for (int h = 0; h < 2; h++)
#pragma unroll
                for (int j = 0; j < 2; j++)
#pragma unroll
                    for (int c = 0; c < 4; c++) acc[h][j][c] = 0.f;

#pragma unroll 4
            for (int kb = 0; kb < 32; kb++) {
                const int kk = kb * 8;
                uint32_t a00 = St[(wrB + qr     )*260 + kk + qc];
                uint32_t a01 = St[(wrB + qr + 8 )*260 + kk + qc];
                uint32_t a02 = St[(wrB + qr     )*260 + kk + qc + 4];
                uint32_t a03 = St[(wrB + qr + 8 )*260 + kk + qc + 4];
                uint32_t a10 = St[(wrB + qr + 16)*260 + kk + qc];
                uint32_t a11 = St[(wrB + qr + 24)*260 + kk + qc];
                uint32_t a12 = St[(wrB + qr + 16)*260 + kk + qc + 4];
                uint32_t a13 = St[(wrB + qr + 24)*260 + kk + qc + 4];
#pragma unroll
                for (int j = 0; j < 2; j++) {
                    const int n = wcB + j*8 + qr;
                    uint32_t b0 = W2s[(kk + qc    )*72 + n];
                    uint32_t b1 = W2s[(kk + qc + 4)*72 + n];
                    mma8(acc[0][j], a00, a01, a02, a03, b0, b1);
                    mma8(acc[1][j], a10, a11, a12, a13, b0, b1);
                }
            }
            float* gp = g_part + (size_t)kcB*BSZ*ZZ;
            const int mB = moB*64 + wrB + qr;
#pragma unroll
            for (int h = 0; h < 2; h++) {
#pragma unroll
                for (int j = 0; j < 2; j++) {
                    const int n = noB*64 + wcB + j*8 + qc*2;
                    const int r0 = mB + h*16;
                    *(float2*)&gp[(size_t)r0*ZZ + n]     = make_float2(acc[h][j][0], acc[h][j][1]);
                    *(float2*)&gp[(size_t)(r0+8)*ZZ + n] = make_float2(acc[h][j][2], acc[h][j][3]);
                }
            }
        }
        gridbar(tgt);

        // ============ phase B2: combine + tanh + Euler + row minmax (fp32) ============
        if (wid < 4) {
            const int row = bid*4 + wid;
            const float* zr = g_states + (size_t)t*BSZ*ZZ + (size_t)row*ZZ;
            const float* nr = noise + (size_t)t*BSZ*ZZ + (size_t)row*ZZ;
            const float* dr = g_diff + ((size_t)t*BB + (row >> 3))*ZZ;
            float* pr = g_post + (size_t)t*BSZ*ZZ + (size_t)row*ZZ;
            float* outz = g_states + (size_t)(t+1)*BSZ*ZZ + (size_t)row*ZZ;

            float v8[8];
            float vmin = 3.4e38f, vmax = -3.4e38f;
#pragma unroll
            for (int j = 0; j < 2; j++) {
                const int cb = lane*4 + 128*j;
                float4 s  = *(const float4*)&g_part[0*BSZ*ZZ + (size_t)row*ZZ + cb];
                float4 s1 = *(const float4*)&g_part[1*BSZ*ZZ + (size_t)row*ZZ + cb];
                float4 s2 = *(const float4*)&g_part[2*BSZ*ZZ + (size_t)row*ZZ + cb];
                float4 s3 = *(const float4*)&g_part[3*BSZ*ZZ + (size_t)row*ZZ + cb];
                float4 bb = *(const float4*)&b2[cb];
                float4 zv = *(const float4*)&zr[cb];
                float4 nv = *(const float4*)&nr[cb];
                float4 dv = *(const float4*)&dr[cb];
                float pd0 = 0.1f * tanhf(s.x + s1.x + s2.x + s3.x + bb.x);
                float pd1 = 0.1f * tanhf(s.y + s1.y + s2.y + s3.y + bb.y);
                float pd2 = 0.1f * tanhf(s.z + s1.z + s2.z + s3.z + bb.z);
                float pd3 = 0.1f * tanhf(s.w + s1.w + s2.w + s3.w + bb.w);
                *(float4*)&pr[cb] = make_float4(pd0, pd1, pd2, pd3);
                float n0v = zv.x + DT_C*pd0 + SQRT_DT_C*dv.x*nv.x;
                float n1v = zv.y + DT_C*pd1 + SQRT_DT_C*dv.y*nv.y;
                float n2v = zv.z + DT_C*pd2 + SQRT_DT_C*dv.z*nv.z;
                float n3v = zv.w + DT_C*pd3 + SQRT_DT_C*dv.w*nv.w;
                v8[j*4+0] = n0v; v8[j*4+1] = n1v; v8[j*4+2] = n2v; v8[j*4+3] = n3v;
                vmin = fminf(vmin, fminf(fminf(n0v, n1v), fminf(n2v, n3v)));
                vmax = fmaxf(vmax, fmaxf(fmaxf(n0v, n1v), fmaxf(n2v, n3v)));
            }
#pragma unroll
            for (int o = 16; o > 0; o >>= 1) {
                vmin = fminf(vmin, __shfl_xor_sync(0xffffffffu, vmin, o));
                vmax = fmaxf(vmax, __shfl_xor_sync(0xffffffffu, vmax, o));
            }
            const float inv = 1.f / (vmax - vmin);
#pragma unroll
            for (int j = 0; j < 2; j++) {
                const int cb = lane*4 + 128*j;
                *(float4*)&outz[cb] = make_float4((v8[j*4+0]-vmin)*inv, (v8[j*4+1]-vmin)*inv,
                                                  (v8[j*4+2]-vmin)*inv, (v8[j*4+3]-vmin)*inv);
            }
        }
        gridbar(tgt);
    }
}

// ---------------- small kernels ----------------
__global__ void reset_kernel()
{
    if (threadIdx.x < 32) g_cnt[threadIdx.x << 5] = 0u;
}

__global__ void mt_kernel(const float* __restrict__ M)
{
    int r = blockIdx.x * blockDim.x + threadIdx.x;
    if (r < TT * BB) {
        const float* p = M + (size_t)r * DD;
        float s = 0.f;
        for (int d = 0; d < DD; d++) s += p[d];
        g_Mt[r] = s * (1.f / DD);
    }
}

__global__ void z0_kernel(const float* __restrict__ cov,
                          const float* __restrict__ w1, const float* __restrict__ b1,
                          const float* __restrict__ w2, const float* __restrict__ b2)
{
    int b = blockIdx.x;
    __shared__ float cv[16];
    __shared__ float hid[64];
    if (threadIdx.x < 16) cv[threadIdx.x] = cov[b * 16 + threadIdx.x];
    __syncthreads();
    if (threadIdx.x < 64) {
        float s = b1[threadIdx.x];
        for (int i = 0; i < 16; i++) s += cv[i] * w1[i * 64 + threadIdx.x];
        hid[threadIdx.x] = fmaxf(s, 0.f);
    }
    __syncthreads();
    int n = threadIdx.x;
    float s = b2[n];
    for (int j = 0; j < 64; j++) s += hid[j] * w2[j * 256 + n];
    float z = tanhf(s);
    for (int ss = 0; ss < SS; ss++)
        g_states[(size_t)(b * SS + ss) * ZZ + n] = z;
}

__global__ void out_copy_kernel(float* __restrict__ out)
{
    int i = blockIdx.x * 256 + threadIdx.x;
    out[i] = g_states[(size_t)TT * BSZ * ZZ + i];
}

__global__ void scal_kernel(float* __restrict__ out)
{
    __shared__ float red[256];
    int tid = threadIdx.x;
    float s = 0.f;
    for (int i = tid; i < KLD_PARTS; i += 256) s += g_kld_part[i];
    red[tid] = s;
    __syncthreads();
    for (int o = 128; o > 0; o >>= 1) { if (tid < o) red[tid] += red[tid + o]; __syncthreads(); }
    float kldsum = red[0];
    __syncthreads();
    s = 0.f;
    for (int i = tid; i < RECON_PARTS; i += 256) s += g_recon_part[i];
    red[tid] = s;
    __syncthreads();
    for (int o = 128; o > 0; o >>= 1) { if (tid < o) red[tid] += red[tid + o]; __syncthreads(); }
    if (tid == 0) {
        float reconsum = red[0];
        float lk = (0.5f * DT_C / (float)(BB * SS)) * kldsum;
        float lr = reconsum * (1.f / (float)(BB * SS));
        out[131072] = lr + lk;   // loss_total
        out[131073] = lr;        // loss_recon
        out[131074] = lk;        // loss_kld
    }
}

// ---------------- launch ----------------
extern "C" void kernel_launch(void* const* d_in, const int* in_sizes, int n_in,
                              void* d_out, int out_size)
{
    (void)in_sizes; (void)n_in; (void)out_size;
    const float* X        = (const float*)d_in[0];
    const float* M        = (const float*)d_in[1];
    const float* cov      = (const float*)d_in[2];
    const float* path_h   = (const float*)d_in[3];
    const float* path_hpos= (const float*)d_in[4];
    const float* noise    = (const float*)d_in[5];
    const float* drift_w1 = (const float*)d_in[6];
    const float* drift_b1 = (const float*)d_in[7];
    const float* drift_w2 = (const float*)d_in[8];
    const float* drift_b2 = (const float*)d_in[9];
    const float* diff_w1  = (const float*)d_in[10];
    const float* diff_b1  = (const float*)d_in[11];
    const float* diff_w2  = (const float*)d_in[12];
    const float* diff_b2  = (const float*)d_in[13];
    const float* p_w1     = (const float*)d_in[14];
    const float* p_b1     = (const float*)d_in[15];
    const float* p_w2     = (const float*)d_in[16];
    const float* p_b2     = (const float*)d_in[17];
    const float* cov_w1   = (const float*)d_in[18];
    const float* cov_b1   = (const float*)d_in[19];
    const float* cov_w2   = (const float*)d_in[20];
    const float* cov_b2   = (const float*)d_in[21];
    float* out = (float*)d_out;

    float *hprior, *hpost, *ppart, *dtmp, *diffp, *states, *zw, *post, *A3, *kldp, *reconp, *Mtp;
    cudaGetSymbolAddress((void**)&hprior, g_hprior);
    cudaGetSymbolAddress((void**)&hpost,  g_hpost);
    cudaGetSymbolAddress((void**)&ppart,  g_ppart);
    cudaGetSymbolAddress((void**)&dtmp,   g_dtmp);
    cudaGetSymbolAddress((void**)&diffp,  g_diff);
    cudaGetSymbolAddress((void**)&states, g_states);
    cudaGetSymbolAddress((void**)&zw,     g_zw);
    cudaGetSymbolAddress((void**)&post,   g_post);
    cudaGetSymbolAddress((void**)&A3,     g_A3);
    cudaGetSymbolAddress((void**)&kldp,   g_kld_part);
    cudaGetSymbolAddress((void**)&reconp, g_recon_part);
    cudaGetSymbolAddress((void**)&Mtp,    g_Mt);

    static int smem_set = 0;
    if (!smem_set) {
        cudaFuncSetAttribute(scan_kernel,
                             cudaFuncAttributeMaxDynamicSharedMemorySize, SMEM_SCAN);
        smem_set = 1;
    }

    // ---- precompute (parallel over T) ----
    reset_kernel<<<1, 32>>>();
    gemm_t<PRO_PLAIN, EPI_STORE><<<dim3(16, 100), 256>>>(
        path_h, RR, drift_w1, HH, hprior, HH, RR, drift_b1,
        nullptr, nullptr, nullptr, nullptr);
    gemm_t<PRO_PLAIN, EPI_STORE><<<dim3(16, 100), 256>>>(
        path_hpos, RR, drift_w1, HH, hpost, HH, RR, drift_b1,
        nullptr, nullptr, nullptr, nullptr);
    gemm_t<PRO_PLAIN, EPI_STORE><<<dim3(16, 100), 256>>>(
        path_h, RR, p_w1, HH, ppart, HH, RR, p_b1,
        nullptr, nullptr, nullptr, nullptr);
    gemm_t<PRO_PLAIN, EPI_RELU><<<dim3(16, 100), 256>>>(
        path_h, RR, diff_w1, HH, dtmp, HH, RR, diff_b1,
        nullptr, nullptr, nullptr, nullptr);
    gemm_t<PRO_PLAIN, EPI_EXP><<<dim3(4, 100), 256>>>(
        dtmp, HH, diff_w2, ZZ, diffp, ZZ, HH, diff_b2,
        nullptr, nullptr, nullptr, nullptr);
    mt_kernel<<<(TT * BB + 255) / 256, 256>>>(M);
    z0_kernel<<<BB, 256>>>(cov, cov_w1, cov_b1, cov_w2, cov_b2);

    // ---- sequential scan: ONE persistent kernel for all 200 steps ----
    scan_kernel<<<SCAN_BLOCKS, SCAN_THREADS, SMEM_SCAN>>>(
        drift_w1 + (size_t)RR * HH, drift_w2, drift_b2, noise);

    // ---- batch epilogue (parallel over all T) ----
    gemm_t<PRO_ADDRELU, EPI_KLD><<<dim3(4, 800), 256>>>(
        zw, HH, drift_w2, ZZ, nullptr, 0, HH, drift_b2,
        hprior, post, diffp, kldp);
    gemm_t<PRO_PLAIN, EPI_BCASTRELU><<<dim3(16, 800), 256>>>(
        states + (size_t)BSZ * ZZ, ZZ, p_w1 + (size_t)RR * HH, HH,
        A3, HH, ZZ, nullptr, ppart, nullptr, nullptr, nullptr);
    gemm_t<PRO_PLAIN, EPI_RECON><<<dim3(2, 800), 256>>>(
        A3, HH, p_w2, DD, nullptr, 0, HH, p_b2,
        X, Mtp, nullptr, reconp);

    // ---- output: z_final then (total, recon, kld) ----
    out_copy_kernel<<<512, 256>>>(out);
    scal_kernel<<<1, 256>>>(out);
}

// round 13
// speedup vs baseline: 1.3459x; 1.3459x over previous
#include <cuda_runtime.h>
#include <math.h>
#include <stdint.h>

#define TT 200
#define BB 64
#define SS 8
#define DD 128
#define RR 512
#define ZZ 256
#define HH 1024
#define BSZ (BB*SS)            /* 512 rows per step */
#define DT_C 0.05f
#define SQRT_DT_C 0.223606797749979f
#define LOG2PI_C 1.8378770664093453f

#define KLD_PARTS  (800*4)
#define RECON_PARTS (800*2)

#define SCAN_BLOCKS 128
#define SCAN_THREADS 128

// ---------------- device scratch (static, allocation-free) ----------------
__device__ float g_hprior[TT*BB*HH];        // h@drift_w1[:R] + b1
__device__ float g_hpost [TT*BB*HH];        // hpos@drift_w1[:R] + b1
__device__ float g_ppart [TT*BB*HH];        // h@p_w1[:R] + p_b1
__device__ float g_dtmp  [TT*BB*HH];        // relu(h@diff_w1+b1), tf32-rounded
__device__ float g_diff  [TT*BB*ZZ];        // exp(diff MLP)
__device__ float g_Mt    [TT*BB];
__device__ float g_states[(TT+1)*BSZ*ZZ];   // z trajectory (normalized)
__device__ float g_zw    [TT*BSZ*HH];       // z_t @ drift_w1[R:]
__device__ float g_post  [TT*BSZ*ZZ];       // posterior drift
__device__ float g_A3    [TT*BSZ*HH];       // decoder hidden, tf32-rounded
__device__ float g_part  [4*BSZ*ZZ];        // split-K partials for scan
__device__ float g_kld_part[KLD_PARTS];
__device__ float g_recon_part[RECON_PARTS];
__device__ unsigned g_cnt[32*32];           // spread barrier counters (128B apart)

// tf32 pre-converted copies (rounded-to-nearest once; bit-identical downstream)
__device__ float g_w1tf [(RR+ZZ)*HH];       // drift_w1
__device__ float g_pw1tf[(RR+ZZ)*HH];       // p_w1
__device__ float g_dw1tf[RR*HH];            // diff_w1
__device__ float g_dfw2tf[HH*ZZ];           // diff_w2
__device__ float g_drw2tf[HH*ZZ];           // drift_w2
__device__ float g_pw2tf[HH*DD];            // p_w2
__device__ float g_phtf [TT*BB*RR];         // path_h
__device__ float g_hptf [TT*BB*RR];         // path_hpos

// ---------------- tf32 / async helpers ----------------
__device__ __forceinline__ uint32_t f2tf(float f)
{
    uint32_t u;
    asm("cvt.rna.tf32.f32 %0, %1;" : "=r"(u) : "f"(f));
    return u;
}

__device__ __forceinline__ uint32_t f2tf_u(uint32_t raw)
{
    return f2tf(__uint_as_float(raw));
}

__device__ __forceinline__ void mma8(float* c,
    uint32_t a0, uint32_t a1, uint32_t a2, uint32_t a3,
    uint32_t b0, uint32_t b1)
{
    asm("mma.sync.aligned.m16n8k8.row.col.f32.tf32.tf32.f32 "
        "{%0,%1,%2,%3},{%4,%5,%6,%7},{%8,%9},{%0,%1,%2,%3};"
        : "+f"(c[0]), "+f"(c[1]), "+f"(c[2]), "+f"(c[3])
        : "r"(a0), "r"(a1), "r"(a2), "r"(a3), "r"(b0), "r"(b1));
}

__device__ __forceinline__ void cp16(uint32_t smem_dst, const void* gsrc)
{
    asm volatile("cp.async.cg.shared.global [%0], [%1], 16;\n"
                 :: "r"(smem_dst), "l"(gsrc));
}
#define CP_COMMIT() asm volatile("cp.async.commit_group;\n" ::: "memory")
#define CP_WAIT1()  asm volatile("cp.async.wait_group 1;\n" ::: "memory")
#define CP_WAIT0()  asm volatile("cp.async.wait_group 0;\n" ::: "memory")

// ---------------- generic 128x64 tf32 GEMM with fused pro/epilogues ------
#define PRO_PLAIN 0
#define PRO_ADDRELU 1      // A := relu(A + aux[(m>>3)*H + k])
#define EPI_STORE 0        // C = acc (+bias)
#define EPI_RELU  1
#define EPI_EXP   2
#define EPI_BCASTRELU 3    // C = relu(acc + aux[(m>>3)*H + n])
#define EPI_KLD   4        // reduce ((0.1 tanh(acc+b)-post)/diff)^2
#define EPI_RECON 5        // reduce 0.5(log2pi+(X-(acc+b))^2)*Mt

// ATF/BTF: A/B already tf32-rounded (skip consume-time cvt). STF: store tf32-rounded.
template<int PRO, int EPI, int ATF, int BTF, int STF>
__global__ void __launch_bounds__(256) gemm_t(
    const float* __restrict__ A, int lda,
    const float* __restrict__ Bm, int ldb,
    float* __restrict__ C, int ldc, int K,
    const float* __restrict__ bias,
    const float* __restrict__ aux,
    const float* __restrict__ aux2,
    const float* __restrict__ aux3,
    float* __restrict__ part)
{
    constexpr int AW = 36;            // A smem row stride (words), %32=4
    constexpr int BW = 72;            // B smem row stride (words), %32=8
    constexpr int ASZ = 128 * AW;
    constexpr int BSZW = 32 * BW;
    constexpr int NBUF = (PRO == PRO_PLAIN) ? 2 : 1;
    __shared__ uint32_t sm[NBUF * (ASZ + BSZW)];

    const int tid = threadIdx.x;
    const int m0 = blockIdx.y * 128, n0 = blockIdx.x * 64;
    const int wid = tid >> 5, lane = tid & 31;
    const int wm = (wid & 3) * 32;     // warp row offset (4 warps along m)
    const int wn = (wid >> 2) * 32;    // warp col offset (2 warps along n)
    const int qr = lane >> 2;          // 0..7
    const int qc = lane & 3;           // 0..3

    float acc[2][4][4];
#pragma unroll
    for (int h = 0; h < 2; h++)
#pragma unroll
        for (int j = 0; j < 4; j++)
#pragma unroll
            for (int c = 0; c < 4; c++) acc[h][j][c] = 0.f;

    if (PRO == PRO_PLAIN) {
        const uint32_t smb = (uint32_t)__cvta_generic_to_shared(sm);
        auto stage = [&](int k0, int b) {
#pragma unroll
            for (int i = 0; i < 4; i++) {            // A: 128 rows x 32 k
                int slot = tid + 256 * i;
                int row = slot >> 3, k4 = (slot & 7) << 2;
                cp16(smb + (uint32_t)(b * (ASZ + BSZW) + row * AW + k4) * 4,
                     &A[(size_t)(m0 + row) * lda + k0 + k4]);
            }
#pragma unroll
            for (int i = 0; i < 2; i++) {            // B: 32 rows x 64 n
                int slot = tid + 256 * i;
                int row = slot >> 4, n4 = (slot & 15) << 2;
                cp16(smb + (uint32_t)(b * (ASZ + BSZW) + ASZ + row * BW + n4) * 4,
                     &Bm[(size_t)(k0 + row) * ldb + n0 + n4]);
            }
            CP_COMMIT();
        };

        stage(0, 0);
        int buf = 0;
        for (int k0 = 0; k0 < K; k0 += 32) {
            if (k0 + 32 < K) stage(k0 + 32, buf ^ 1);
            if (k0 + 32 < K) { CP_WAIT1(); } else { CP_WAIT0(); }
            __syncthreads();
            const uint32_t* As = sm + buf * (ASZ + BSZW);
            const uint32_t* Bs = As + ASZ;
#pragma unroll
            for (int k8 = 0; k8 < 4; k8++) {
                const int kk = k8 * 8;
                uint32_t a00 = ATF ? As[(wm + qr     ) * AW + kk + qc]     : f2tf_u(As[(wm + qr     ) * AW + kk + qc]);
                uint32_t a01 = ATF ? As[(wm + qr + 8 ) * AW + kk + qc]     : f2tf_u(As[(wm + qr + 8 ) * AW + kk + qc]);
                uint32_t a02 = ATF ? As[(wm + qr     ) * AW + kk + qc + 4] : f2tf_u(As[(wm + qr     ) * AW + kk + qc + 4]);
                uint32_t a03 = ATF ? As[(wm + qr + 8 ) * AW + kk + qc + 4] : f2tf_u(As[(wm + qr + 8 ) * AW + kk + qc + 4]);
                uint32_t a10 = ATF ? As[(wm + qr + 16) * AW + kk + qc]     : f2tf_u(As[(wm + qr + 16) * AW + kk + qc]);
                uint32_t a11 = ATF ? As[(wm + qr + 24) * AW + kk + qc]     : f2tf_u(As[(wm + qr + 24) * AW + kk + qc]);
                uint32_t a12 = ATF ? As[(wm + qr + 16) * AW + kk + qc + 4] : f2tf_u(As[(wm + qr + 16) * AW + kk + qc + 4]);
                uint32_t a13 = ATF ? As[(wm + qr + 24) * AW + kk + qc + 4] : f2tf_u(As[(wm + qr + 24) * AW + kk + qc + 4]);
#pragma unroll
                for (int j = 0; j < 4; j++) {
                    const int cn = wn + j * 8 + qr;
                    uint32_t b0 = BTF ? Bs[(kk + qc    ) * BW + cn] : f2tf_u(Bs[(kk + qc    ) * BW + cn]);
                    uint32_t b1 = BTF ? Bs[(kk + qc + 4) * BW + cn] : f2tf_u(Bs[(kk + qc + 4) * BW + cn]);
                    mma8(acc[0][j], a00, a01, a02, a03, b0, b1);
                    mma8(acc[1][j], a10, a11, a12, a13, b0, b1);
                }
            }
            __syncthreads();
            buf ^= 1;
        }
    } else {
        // synchronous staged path (PRO_ADDRELU)
        uint32_t* As = sm;
        uint32_t* Bs = sm + ASZ;
        const int arow = tid >> 1;
        const int ab   = (tid & 1) * 16;
        const int brow = tid >> 3;
        const int bn   = (tid & 7) * 8;
        for (int k0 = 0; k0 < K; k0 += 32) {
#pragma unroll
            for (int i = 0; i < 4; i++) {
                float4 av = *(const float4*)&A[(size_t)(m0 + arow) * lda + k0 + ab + 4*i];
                const float4 hv = *(const float4*)&aux[(size_t)((m0 + arow) >> 3) * HH + k0 + ab + 4*i];
                av.x = fmaxf(av.x + hv.x, 0.f); av.y = fmaxf(av.y + hv.y, 0.f);
                av.z = fmaxf(av.z + hv.z, 0.f); av.w = fmaxf(av.w + hv.w, 0.f);
                uint4 t;
                t.x = f2tf(av.x); t.y = f2tf(av.y); t.z = f2tf(av.z); t.w = f2tf(av.w);
                *(uint4*)&As[arow * AW + ab + 4*i] = t;
            }
#pragma unroll
            for (int i = 0; i < 2; i++) {
                float4 bv = *(const float4*)&Bm[(size_t)(k0 + brow) * ldb + n0 + bn + 4*i];
                uint4 t;
                t.x = f2tf(bv.x); t.y = f2tf(bv.y); t.z = f2tf(bv.z); t.w = f2tf(bv.w);
                *(uint4*)&Bs[brow * BW + bn + 4*i] = t;
            }
            __syncthreads();
#pragma unroll
            for (int k8 = 0; k8 < 4; k8++) {
                const int kk = k8 * 8;
                uint32_t a00 = As[(wm + qr     ) * AW + kk + qc];
                uint32_t a01 = As[(wm + qr + 8 ) * AW + kk + qc];
                uint32_t a02 = As[(wm + qr     ) * AW + kk + qc + 4];
                uint32_t a03 = As[(wm + qr + 8 ) * AW + kk + qc + 4];
                uint32_t a10 = As[(wm + qr + 16) * AW + kk + qc];
                uint32_t a11 = As[(wm + qr + 24) * AW + kk + qc];
                uint32_t a12 = As[(wm + qr + 16) * AW + kk + qc + 4];
                uint32_t a13 = As[(wm + qr + 24) * AW + kk + qc + 4];
#pragma unroll
                for (int j = 0; j < 4; j++) {
                    const int cn = wn + j * 8 + qr;
                    uint32_t b0 = Bs[(kk + qc    ) * BW + cn];
                    uint32_t b1 = Bs[(kk + qc + 4) * BW + cn];
                    mma8(acc[0][j], a00, a01, a02, a03, b0, b1);
                    mma8(acc[1][j], a10, a11, a12, a13, b0, b1);
                }
            }
            __syncthreads();
        }
    }

    const int mA = m0 + wm + qr;
    const int nB0 = n0 + wn + qc * 2;

    if (EPI <= 3) {
        const bool hasb = (bias != nullptr);
#pragma unroll
        for (int h = 0; h < 2; h++) {
#pragma unroll
            for (int j = 0; j < 4; j++) {
                const int n = nB0 + j * 8;
                const int r0 = mA + h * 16, r1 = r0 + 8;
                float v[4] = {acc[h][j][0], acc[h][j][1], acc[h][j][2], acc[h][j][3]};
                const int mm[4] = {r0, r0, r1, r1};
                const int nn[4] = {n, n + 1, n, n + 1};
#pragma unroll
                for (int c = 0; c < 4; c++) {
                    if (hasb) v[c] += bias[nn[c]];
                    if (EPI == EPI_RELU) v[c] = fmaxf(v[c], 0.f);
                    if (EPI == EPI_EXP)  v[c] = expf(v[c]);
                    if (EPI == EPI_BCASTRELU)
                        v[c] = fmaxf(v[c] + aux[(size_t)(mm[c] >> 3) * HH + nn[c]], 0.f);
                    if (STF) v[c] = __uint_as_float(f2tf(v[c]));
                }
                *(float2*)&C[(size_t)r0 * ldc + n] = make_float2(v[0], v[1]);
                *(float2*)&C[(size_t)r1 * ldc + n] = make_float2(v[2], v[3]);
            }
        }
    } else {
        float s = 0.f;
#pragma unroll
        for (int h = 0; h < 2; h++) {
#pragma unroll
            for (int j = 0; j < 4; j++) {
                const int n = nB0 + j * 8;
                const int r0 = mA + h * 16, r1 = r0 + 8;
                const int mm[4] = {r0, r0, r1, r1};
                const int nn[4] = {n, n + 1, n, n + 1};
#pragma unroll
                for (int c = 0; c < 4; c++) {
                    float v = acc[h][j][c] + bias[nn[c]];
                    if (EPI == EPI_KLD) {
                        float pr = 0.1f * tanhf(v);
                        float e = (pr - aux2[(size_t)mm[c] * ZZ + nn[c]]) /
                                  aux3[(size_t)(mm[c] >> 3) * ZZ + nn[c]];
                        s += e * e;
                    } else { // EPI_RECON
                        float d = aux[(size_t)(mm[c] >> 3) * DD + nn[c]] - v;
                        float nll = 0.5f * (LOG2PI_C + d * d);
                        s += nll * aux2[mm[c] >> 3];
                    }
                }
            }
        }
        __shared__ float red[256];
        red[tid] = s;
        __syncthreads();
        for (int o = 128; o > 0; o >>= 1) {
            if (tid < o) red[tid] += red[tid + o];
            __syncthreads();
        }
        if (tid == 0) part[blockIdx.y * gridDim.x + blockIdx.x] = red[0];
    }
}

// ---------------- persistent scan kernel (tf32, 4 warps, 32x32 tiles) -----
#define SMEM_SCAN ((256*72*2 + 64*260) * 4)

__device__ __forceinline__ void gridbar(unsigned& tgt)
{
    tgt += SCAN_BLOCKS;
    __syncthreads();
    if (threadIdx.x == 0) {
        __threadfence();
        atomicAdd(&g_cnt[(blockIdx.x & 31) << 5], 1u);
    }
    if (threadIdx.x < 32) {
        unsigned s;
        do {
            s = *(volatile unsigned*)&g_cnt[threadIdx.x << 5];
#pragma unroll
            for (int o = 16; o > 0; o >>= 1)
                s += __shfl_xor_sync(0xffffffffu, s, o);
        } while (s < tgt);
        __threadfence();
    }
    __syncthreads();
}

__global__ void __launch_bounds__(SCAN_THREADS, 1) scan_kernel(
    const float* __restrict__ w1z,      // g_w1tf + RR*HH (tf32 bits)
    const float* __restrict__ w2,       // g_drw2tf (tf32 bits)
    const float* __restrict__ b2,       // drift_b2
    const float* __restrict__ noise)
{
    extern __shared__ uint32_t smu[];
    uint32_t* W1s = smu;                     // [256][72]
    uint32_t* W2s = smu + 256*72;            // [256][72]
    uint32_t* St  = smu + 2*256*72;          // [64][260]

    const int tid = threadIdx.x;
    const int bid = blockIdx.x;
    const int wid = tid >> 5, lane = tid & 31;
    const int qr = lane >> 2;   // 0..7
    const int qc = lane & 3;    // 0..3

    const int bmA = bid >> 4;          // 0..7
    const int bnA = bid & 15;          // 0..15
    const int wmA = (wid & 1) * 32;
    const int wnA = (wid >> 1) * 32;

    const int kcB = bid & 3;
    const int moB = (bid >> 2) >> 2;
    const int noB = (bid >> 2) & 3;
    const int wrB = (wid & 1) * 32;
    const int wcB = (wid >> 1) * 32;

    for (int i = tid; i < 256*64; i += SCAN_THREADS) {
        int k = i >> 6, c = i & 63;
        W1s[k*72 + c] = __float_as_uint(w1z[(size_t)k*HH + bnA*64 + c]);
        W2s[k*72 + c] = __float_as_uint(w2[(size_t)(kcB*256 + k)*ZZ + noB*64 + c]);
    }
    __syncthreads();

    unsigned tgt = 0;

    for (int t = 0; t < TT; t++) {
        const float* z = g_states + (size_t)t*BSZ*ZZ;
        float* zwt = g_zw + (size_t)t*BSZ*HH;

        // ============ phase A: zw[t] = z_t @ w1z (tf32 mma) ============
        {
            for (int i = tid; i < 64*64; i += SCAN_THREADS) {
                int row = i >> 6, q = (i & 63) << 2;
                float4 f = *(const float4*)&z[(size_t)(bmA*64 + row)*ZZ + q];
                uint4 u;
                u.x = f2tf(f.x); u.y = f2tf(f.y); u.z = f2tf(f.z); u.w = f2tf(f.w);
                *(uint4*)&St[row*260 + q] = u;
            }
            __syncthreads();

            float acc[2][4][4];
#pragma unroll
            for (int h = 0; h < 2; h++)
#pragma unroll
                for (int j = 0; j < 4; j++)
#pragma unroll
                    for (int c = 0; c < 4; c++) acc[h][j][c] = 0.f;

#pragma unroll 4
            for (int kb = 0; kb < 32; kb++) {
                const int kk = kb * 8;
                uint32_t a00 = St[(wmA + qr     )*260 + kk + qc];
                uint32_t a01 = St[(wmA + qr + 8 )*260 + kk + qc];
                uint32_t a02 = St[(wmA + qr     )*260 + kk + qc + 4];
                uint32_t a03 = St[(wmA + qr + 8 )*260 + kk + qc + 4];
                uint32_t a10 = St[(wmA + qr + 16)*260 + kk + qc];
                uint32_t a11 = St[(wmA + qr + 24)*260 + kk + qc];
                uint32_t a12 = St[(wmA + qr + 16)*260 + kk + qc + 4];
                uint32_t a13 = St[(wmA + qr + 24)*260 + kk + qc + 4];
#pragma unroll
                for (int j = 0; j < 4; j++) {
                    const int n = wnA + j*8 + qr;
                    uint32_t b0 = W1s[(kk + qc    )*72 + n];
                    uint32_t b1 = W1s[(kk + qc + 4)*72 + n];
                    mma8(acc[0][j], a00, a01, a02, a03, b0, b1);
                    mma8(acc[1][j], a10, a11, a12, a13, b0, b1);
                }
            }
            const int mA = bmA*64 + wmA + qr;
#pragma unroll
            for (int h = 0; h < 2; h++) {
#pragma unroll
                for (int j = 0; j < 4; j++) {
                    const int n = bnA*64 + wnA + j*8 + qc*2;
                    const int r0 = mA + h*16;
                    *(float2*)&zwt[(size_t)r0*HH + n]     = make_float2(acc[h][j][0], acc[h][j][1]);
                    *(float2*)&zwt[(size_t)(r0+8)*HH + n] = make_float2(acc[h][j][2], acc[h][j][3]);
                }
            }
        }
        gridbar(tgt);

        // ============ phase B1: partial relu(zw+hpost)@W2 (tf32 mma) ============
        {
            const float* hp = g_hpost + (size_t)t*BB*HH;
            for (int i = tid; i < 64*64; i += SCAN_THREADS) {
                int row = i >> 6, q = (i & 63) << 2;
                int gk = kcB*256 + q;
                float4 f  = *(const float4*)&zwt[(size_t)(moB*64 + row)*HH + gk];
                float4 h4 = *(const float4*)&hp[(size_t)((moB*64 + row) >> 3)*HH + gk];
                uint4 u;
                u.x = f2tf(fmaxf(f.x + h4.x, 0.f));
                u.y = f2tf(fmaxf(f.y + h4.y, 0.f));
                u.z = f2tf(fmaxf(f.z + h4.z, 0.f));
                u.w = f2tf(fmaxf(f.w + h4.w, 0.f));
                *(uint4*)&St[row*260 + q] = u;
            }
            __syncthreads();

            float acc[2][4][4];
#pragma unroll
            for (int h = 0; h < 2; h++)
#pragma unroll
                for (int j = 0; j < 4; j++)
#pragma unroll
                    for (int c = 0; c < 4; c++) acc[h][j][c] = 0.f;

#pragma unroll 4
            for (int kb = 0; kb < 32; kb++) {
                const int kk = kb * 8;
                uint32_t a00 = St[(wrB + qr     )*260 + kk + qc];
                uint32_t a01 = St[(wrB + qr + 8 )*260 + kk + qc];
                uint32_t a02 = St[(wrB + qr     )*260 + kk + qc + 4];
                uint32_t a03 = St[(wrB + qr + 8 )*260 + kk + qc + 4];
                uint32_t a10 = St[(wrB + qr + 16)*260 + kk + qc];
                uint32_t a11 = St[(wrB + qr + 24)*260 + kk + qc];
                uint32_t a12 = St[(wrB + qr + 16)*260 + kk + qc + 4];
                uint32_t a13 = St[(wrB + qr + 24)*260 + kk + qc + 4];
#pragma unroll
                for (int j = 0; j < 4; j++) {
                    const int n = wcB + j*8 + qr;
                    uint32_t b0 = W2s[(kk + qc    )*72 + n];
                    uint32_t b1 = W2s[(kk + qc + 4)*72 + n];
                    mma8(acc[0][j], a00, a01, a02, a03, b0, b1);
                    mma8(acc[1][j], a10, a11, a12, a13, b0, b1);
                }
            }
            float* gp = g_part + (size_t)kcB*BSZ*ZZ;
            const int mB = moB*64 + wrB + qr;
#pragma unroll
            for (int h = 0; h < 2; h++) {
#pragma unroll
                for (int j = 0; j < 4; j++) {
                    const int n = noB*64 + wcB + j*8 + qc*2;
                    const int r0 = mB + h*16;
                    *(float2*)&gp[(size_t)r0*ZZ + n]     = make_float2(acc[h][j][0], acc[h][j][1]);
                    *(float2*)&gp[(size_t)(r0+8)*ZZ + n] = make_float2(acc[h][j][2], acc[h][j][3]);
                }
            }
        }
        gridbar(tgt);

        // ============ phase B2: combine + tanh + Euler + row minmax (fp32) ============
        {
            const int row = bid*4 + wid;
            const float* zr = g_states + (size_t)t*BSZ*ZZ + (size_t)row*ZZ;
            const float* nr = noise + (size_t)t*BSZ*ZZ + (size_t)row*ZZ;
            const float* dr = g_diff + ((size_t)t*BB + (row >> 3))*ZZ;
            float* pr = g_post + (size_t)t*BSZ*ZZ + (size_t)row*ZZ;
            float* outz = g_states + (size_t)(t+1)*BSZ*ZZ + (size_t)row*ZZ;

            float v8[8];
            float vmin = 3.4e38f, vmax = -3.4e38f;
#pragma unroll
            for (int j = 0; j < 2; j++) {
                const int cb = lane*4 + 128*j;
                float4 s  = *(const float4*)&g_part[0*BSZ*ZZ + (size_t)row*ZZ + cb];
                float4 s1 = *(const float4*)&g_part[1*BSZ*ZZ + (size_t)row*ZZ + cb];
                float4 s2 = *(const float4*)&g_part[2*BSZ*ZZ + (size_t)row*ZZ + cb];
                float4 s3 = *(const float4*)&g_part[3*BSZ*ZZ + (size_t)row*ZZ + cb];
                float4 bb = *(const float4*)&b2[cb];
                float4 zv = *(const float4*)&zr[cb];
                float4 nv = *(const float4*)&nr[cb];
                float4 dv = *(const float4*)&dr[cb];
                float pd0 = 0.1f * tanhf(s.x + s1.x + s2.x + s3.x + bb.x);
                float pd1 = 0.1f * tanhf(s.y + s1.y + s2.y + s3.y + bb.y);
                float pd2 = 0.1f * tanhf(s.z + s1.z + s2.z + s3.z + bb.z);
                float pd3 = 0.1f * tanhf(s.w + s1.w + s2.w + s3.w + bb.w);
                *(float4*)&pr[cb] = make_float4(pd0, pd1, pd2, pd3);
                float n0v = zv.x + DT_C*pd0 + SQRT_DT_C*dv.x*nv.x;
                float n1v = zv.y + DT_C*pd1 + SQRT_DT_C*dv.y*nv.y;
                float n2v = zv.z + DT_C*pd2 + SQRT_DT_C*dv.z*nv.z;
                float n3v = zv.w + DT_C*pd3 + SQRT_DT_C*dv.w*nv.w;
                v8[j*4+0] = n0v; v8[j*4+1] = n1v; v8[j*4+2] = n2v; v8[j*4+3] = n3v;
                vmin = fminf(vmin, fminf(fminf(n0v, n1v), fminf(n2v, n3v)));
                vmax = fmaxf(vmax, fmaxf(fmaxf(n0v, n1v), fmaxf(n2v, n3v)));
            }
#pragma unroll
            for (int o = 16; o > 0; o >>= 1) {
                vmin = fminf(vmin, __shfl_xor_sync(0xffffffffu, vmin, o));
                vmax = fmaxf(vmax, __shfl_xor_sync(0xffffffffu, vmax, o));
            }
            const float inv = 1.f / (vmax - vmin);
#pragma unroll
            for (int j = 0; j < 2; j++) {
                const int cb = lane*4 + 128*j;
                *(float4*)&outz[cb] = make_float4((v8[j*4+0]-vmin)*inv, (v8[j*4+1]-vmin)*inv,
                                                  (v8[j*4+2]-vmin)*inv, (v8[j*4+3]-vmin)*inv);
            }
        }
        gridbar(tgt);
    }
}

// ---------------- weight/activation tf32 pre-conversion (+barrier reset) --
__global__ void convw_kernel(const float* __restrict__ dw1,
                             const float* __restrict__ pw1,
                             const float* __restrict__ dif1,
                             const float* __restrict__ dif2,
                             const float* __restrict__ drw2,
                             const float* __restrict__ pw2,
                             const float* __restrict__ ph,
                             const float* __restrict__ php)
{
    if (blockIdx.x == 0 && threadIdx.x < 32) g_cnt[threadIdx.x << 5] = 0u;
    const long N1 = (long)(RR+ZZ)*HH;
    const long N3 = (long)RR*HH;
    const long N4 = (long)HH*ZZ;
    const long N5 = (long)HH*DD;
    const long N6 = (long)TT*BB*RR;
    const long total = 2*N1 + N3 + 2*N4 + N5 + 2*N6;
    for (long i = (long)blockIdx.x*blockDim.x + threadIdx.x; i < total;
         i += (long)gridDim.x*blockDim.x) {
        long j = i;
        if (j < N1) { g_w1tf[j]  = __uint_as_float(f2tf(dw1[j]));  continue; }
        j -= N1;
        if (j < N1) { g_pw1tf[j] = __uint_as_float(f2tf(pw1[j]));  continue; }
        j -= N1;
        if (j < N3) { g_dw1tf[j] = __uint_as_float(f2tf(dif1[j])); continue; }
        j -= N3;
        if (j < N4) { g_dfw2tf[j] = __uint_as_float(f2tf(dif2[j])); continue; }
        j -= N4;
        if (j < N4) { g_drw2tf[j] = __uint_as_float(f2tf(drw2[j])); continue; }
        j -= N4;
        if (j < N5) { g_pw2tf[j] = __uint_as_float(f2tf(pw2[j]));  continue; }
        j -= N5;
        if (j < N6) { g_phtf[j]  = __uint_as_float(f2tf(ph[j]));   continue; }
        j -= N6;
        g_hptf[j] = __uint_as_float(f2tf(php[j]));
    }
}

// ---------------- small kernels ----------------
__global__ void mt_kernel(const float* __restrict__ M)
{
    int r = blockIdx.x * blockDim.x + threadIdx.x;
    if (r < TT * BB) {
        const float* p = M + (size_t)r * DD;
        float s = 0.f;
        for (int d = 0; d < DD; d++) s += p[d];
        g_Mt[r] = s * (1.f / DD);
    }
}

__global__ void z0_kernel(const float* __restrict__ cov,
                          const float* __restrict__ w1, const float* __restrict__ b1,
                          const float* __restrict__ w2, const float* __restrict__ b2)
{
    int b = blockIdx.x;
    __shared__ float cv[16];
    __shared__ float hid[64];
    if (threadIdx.x < 16) cv[threadIdx.x] = cov[b * 16 + threadIdx.x];
    __syncthreads();
    if (threadIdx.x < 64) {
        float s = b1[threadIdx.x];
        for (int i = 0; i < 16; i++) s += cv[i] * w1[i * 64 + threadIdx.x];
        hid[threadIdx.x] = fmaxf(s, 0.f);
    }
    __syncthreads();
    int n = threadIdx.x;
    float s = b2[n];
    for (int j = 0; j < 64; j++) s += hid[j] * w2[j * 256 + n];
    float z = tanhf(s);
    for (int ss = 0; ss < SS; ss++)
        g_states[(size_t)(b * SS + ss) * ZZ + n] = z;
}

__global__ void out_copy_kernel(float* __restrict__ out)
{
    int i = blockIdx.x * 256 + threadIdx.x;
    out[i] = g_states[(size_t)TT * BSZ * ZZ + i];
}

__global__ void scal_kernel(float* __restrict__ out)
{
    __shared__ float red[256];
    int tid = threadIdx.x;
    float s = 0.f;
    for (int i = tid; i < KLD_PARTS; i += 256) s += g_kld_part[i];
    red[tid] = s;
    __syncthreads();
    for (int o = 128; o > 0; o >>= 1) { if (tid < o) red[tid] += red[tid + o]; __syncthreads(); }
    float kldsum = red[0];
    __syncthreads();
    s = 0.f;
    for (int i = tid; i < RECON_PARTS; i += 256) s += g_recon_part[i];
    red[tid] = s;
    __syncthreads();
    for (int o = 128; o > 0; o >>= 1) { if (tid < o) red[tid] += red[tid + o]; __syncthreads(); }
    if (tid == 0) {
        float reconsum = red[0];
        float lk = (0.5f * DT_C / (float)(BB * SS)) * kldsum;
        float lr = reconsum * (1.f / (float)(BB * SS));
        out[131072] = lr + lk;   // loss_total
        out[131073] = lr;        // loss_recon
        out[131074] = lk;        // loss_kld
    }
}

// ---------------- launch ----------------
extern "C" void kernel_launch(void* const* d_in, const int* in_sizes, int n_in,
                              void* d_out, int out_size)
{
    (void)in_sizes; (void)n_in; (void)out_size;
    const float* X        = (const float*)d_in[0];
    const float* M        = (const float*)d_in[1];
    const float* cov      = (const float*)d_in[2];
    const float* path_h   = (const float*)d_in[3];
    const float* path_hpos= (const float*)d_in[4];
    const float* noise    = (const float*)d_in[5];
    const float* drift_w1 = (const float*)d_in[6];
    const float* drift_b1 = (const float*)d_in[7];
    const float* drift_w2 = (const float*)d_in[8];
    const float* drift_b2 = (const float*)d_in[9];
    const float* diff_w1  = (const float*)d_in[10];
    const float* diff_b1  = (const float*)d_in[11];
    const float* diff_w2  = (const float*)d_in[12];
    const float* diff_b2  = (const float*)d_in[13];
    const float* p_w1     = (const float*)d_in[14];
    const float* p_b1     = (const float*)d_in[15];
    const float* p_w2     = (const float*)d_in[16];
    const float* p_b2     = (const float*)d_in[17];
    const float* cov_w1   = (const float*)d_in[18];
    const float* cov_b1   = (const float*)d_in[19];
    const float* cov_w2   = (const float*)d_in[20];
    const float* cov_b2   = (const float*)d_in[21];
    float* out = (float*)d_out;

    float *hprior, *hpost, *ppart, *dtmp, *diffp, *states, *zw, *post, *A3, *kldp, *reconp, *Mtp;
    float *w1tf, *pw1tf, *dw1tf, *dfw2tf, *drw2tf, *pw2tf, *phtf, *hptf;
    cudaGetSymbolAddress((void**)&hprior, g_hprior);
    cudaGetSymbolAddress((void**)&hpost,  g_hpost);
    cudaGetSymbolAddress((void**)&ppart,  g_ppart);
    cudaGetSymbolAddress((void**)&dtmp,   g_dtmp);
    cudaGetSymbolAddress((void**)&diffp,  g_diff);
    cudaGetSymbolAddress((void**)&states, g_states);
    cudaGetSymbolAddress((void**)&zw,     g_zw);
    cudaGetSymbolAddress((void**)&post,   g_post);
    cudaGetSymbolAddress((void**)&A3,     g_A3);
    cudaGetSymbolAddress((void**)&kldp,   g_kld_part);
    cudaGetSymbolAddress((void**)&reconp, g_recon_part);
    cudaGetSymbolAddress((void**)&Mtp,    g_Mt);
    cudaGetSymbolAddress((void**)&w1tf,   g_w1tf);
    cudaGetSymbolAddress((void**)&pw1tf,  g_pw1tf);
    cudaGetSymbolAddress((void**)&dw1tf,  g_dw1tf);
    cudaGetSymbolAddress((void**)&dfw2tf, g_dfw2tf);
    cudaGetSymbolAddress((void**)&drw2tf, g_drw2tf);
    cudaGetSymbolAddress((void**)&pw2tf,  g_pw2tf);
    cudaGetSymbolAddress((void**)&phtf,   g_phtf);
    cudaGetSymbolAddress((void**)&hptf,   g_hptf);

    static int smem_set = 0;
    if (!smem_set) {
        cudaFuncSetAttribute(scan_kernel,
                             cudaFuncAttributeMaxDynamicSharedMemorySize, SMEM_SCAN);
        smem_set = 1;
    }

    // launch 0: tf32 pre-conversion + barrier reset
    convw_kernel<<<4096, 256>>>(drift_w1, p_w1, diff_w1, diff_w2, drift_w2, p_w2,
                                path_h, path_hpos);
    // launch 1: hpost (needed by scan)
    gemm_t<PRO_PLAIN, EPI_STORE, 1, 1, 0><<<dim3(16, 100), 256>>>(
        hptf, RR, w1tf, HH, hpost, HH, RR, drift_b1,
        nullptr, nullptr, nullptr, nullptr);
    // launch 2: dtmp (tf32-rounded store)
    gemm_t<PRO_PLAIN, EPI_RELU, 1, 1, 1><<<dim3(16, 100), 256>>>(
        phtf, RR, dw1tf, HH, dtmp, HH, RR, diff_b1,
        nullptr, nullptr, nullptr, nullptr);
    // launch 3: diffusion (needed by scan)
    gemm_t<PRO_PLAIN, EPI_EXP, 1, 1, 0><<<dim3(4, 100), 256>>>(
        dtmp, HH, dfw2tf, ZZ, diffp, ZZ, HH, diff_b2,
        nullptr, nullptr, nullptr, nullptr);
    // launch 4: z0
    z0_kernel<<<BB, 256>>>(cov, cov_w1, cov_b1, cov_w2, cov_b2);
    // launch 5: persistent scan  (ncu -s 5 -c 1 profiles THIS)
    scan_kernel<<<SCAN_BLOCKS, SCAN_THREADS, SMEM_SCAN>>>(
        w1tf + (size_t)RR * HH, drw2tf, drift_b2, noise);

    // batch epilogue
    gemm_t<PRO_PLAIN, EPI_STORE, 1, 1, 0><<<dim3(16, 100), 256>>>(
        phtf, RR, w1tf, HH, hprior, HH, RR, drift_b1,
        nullptr, nullptr, nullptr, nullptr);
    gemm_t<PRO_PLAIN, EPI_STORE, 1, 1, 0><<<dim3(16, 100), 256>>>(
        phtf, RR, pw1tf, HH, ppart, HH, RR, p_b1,
        nullptr, nullptr, nullptr, nullptr);
    mt_kernel<<<(TT * BB + 255) / 256, 256>>>(M);
    gemm_t<PRO_ADDRELU, EPI_KLD, 0, 0, 0><<<dim3(4, 800), 256>>>(
        zw, HH, drift_w2, ZZ, nullptr, 0, HH, drift_b2,
        hprior, post, diffp, kldp);
    gemm_t<PRO_PLAIN, EPI_BCASTRELU, 0, 1, 1><<<dim3(16, 800), 256>>>(
        states + (size_t)BSZ * ZZ, ZZ, pw1tf + (size_t)RR * HH, HH,
        A3, HH, ZZ, nullptr, ppart, nullptr, nullptr, nullptr);
    gemm_t<PRO_PLAIN, EPI_RECON, 1, 1, 0><<<dim3(2, 800), 256>>>(
        A3, HH, pw2tf, DD, nullptr, 0, HH, p_b2,
        X, Mtp, nullptr, reconp);

    // output: z_final then (total, recon, kld)
    out_copy_kernel<<<512, 256>>>(out);
    scal_kernel<<<1, 256>>>(out);
}

// round 14
// speedup vs baseline: 1.4782x; 1.0983x over previous
#include <cuda_runtime.h>
#include <math.h>
#include <stdint.h>

#define TT 200
#define BB 64
#define SS 8
#define DD 128
#define RR 512
#define ZZ 256
#define HH 1024
#define BSZ (BB*SS)            /* 512 rows per step */
#define DT_C 0.05f
#define SQRT_DT_C 0.223606797749979f
#define LOG2PI_C 1.8378770664093453f

#define KLD_PARTS  (800*4)
#define RECON_PARTS (800*2)

#define SCAN_BLOCKS 128
#define SCAN_THREADS 128

// ---------------- device scratch (static, allocation-free) ----------------
__device__ float g_hprior[TT*BB*HH];        // h@drift_w1[:R] + b1
__device__ float g_hpost [TT*BB*HH];        // hpos@drift_w1[:R] + b1
__device__ float g_ppart [TT*BB*HH];        // h@p_w1[:R] + p_b1
__device__ float g_dtmp  [TT*BB*HH];        // relu(h@diff_w1+b1), tf32-rounded
__device__ float g_diff  [TT*BB*ZZ];        // exp(diff MLP)
__device__ float g_Mt    [TT*BB];
__device__ float g_states[(TT+1)*BSZ*ZZ];   // z trajectory (normalized, fp32)
__device__ float g_states_tf[(TT+1)*BSZ*ZZ];// z trajectory tf32-rounded bits
__device__ float g_zw    [TT*BSZ*HH];       // z_t @ drift_w1[R:] (raw fp32, for KLD)
__device__ float g_hid   [BSZ*HH];          // tf32 relu(zw+hpost), current step
__device__ float g_post  [TT*BSZ*ZZ];       // posterior drift
__device__ float g_A3    [TT*BSZ*HH];       // decoder hidden, tf32-rounded
__device__ float g_part  [4*BSZ*ZZ];        // split-K partials for scan
__device__ float g_kld_part[KLD_PARTS];
__device__ float g_recon_part[RECON_PARTS];
__device__ unsigned g_cnt[32*32];           // spread barrier counters (128B apart)

// tf32 pre-converted copies (rounded-to-nearest once; bit-identical downstream)
__device__ float g_w1tf [(RR+ZZ)*HH];       // drift_w1
__device__ float g_pw1tf[(RR+ZZ)*HH];       // p_w1
__device__ float g_dw1tf[RR*HH];            // diff_w1
__device__ float g_dfw2tf[HH*ZZ];           // diff_w2
__device__ float g_drw2tf[HH*ZZ];           // drift_w2
__device__ float g_pw2tf[HH*DD];            // p_w2
__device__ float g_phtf [TT*BB*RR];         // path_h
__device__ float g_hptf [TT*BB*RR];         // path_hpos

// ---------------- tf32 / async helpers ----------------
__device__ __forceinline__ uint32_t f2tf(float f)
{
    uint32_t u;
    asm("cvt.rna.tf32.f32 %0, %1;" : "=r"(u) : "f"(f));
    return u;
}

__device__ __forceinline__ uint32_t f2tf_u(uint32_t raw)
{
    return f2tf(__uint_as_float(raw));
}

__device__ __forceinline__ void mma8(float* c,
    uint32_t a0, uint32_t a1, uint32_t a2, uint32_t a3,
    uint32_t b0, uint32_t b1)
{
    asm("mma.sync.aligned.m16n8k8.row.col.f32.tf32.tf32.f32 "
        "{%0,%1,%2,%3},{%4,%5,%6,%7},{%8,%9},{%0,%1,%2,%3};"
        : "+f"(c[0]), "+f"(c[1]), "+f"(c[2]), "+f"(c[3])
        : "r"(a0), "r"(a1), "r"(a2), "r"(a3), "r"(b0), "r"(b1));
}

__device__ __forceinline__ void cp16(uint32_t smem_dst, const void* gsrc)
{
    asm volatile("cp.async.cg.shared.global [%0], [%1], 16;\n"
                 :: "r"(smem_dst), "l"(gsrc));
}
#define CP_COMMIT() asm volatile("cp.async.commit_group;\n" ::: "memory")
#define CP_WAIT1()  asm volatile("cp.async.wait_group 1;\n" ::: "memory")
#define CP_WAIT0()  asm volatile("cp.async.wait_group 0;\n" ::: "memory")

// ---------------- generic 128x64 tf32 GEMM with fused pro/epilogues ------
#define PRO_PLAIN 0
#define PRO_ADDRELU 1      // A := relu(A + aux[(m>>3)*H + k])
#define EPI_STORE 0        // C = acc (+bias)
#define EPI_RELU  1
#define EPI_EXP   2
#define EPI_BCASTRELU 3    // C = relu(acc + aux[(m>>3)*H + n])
#define EPI_KLD   4        // reduce ((0.1 tanh(acc+b)-post)/diff)^2
#define EPI_RECON 5        // reduce 0.5(log2pi+(X-(acc+b))^2)*Mt

// ATF/BTF: A/B already tf32-rounded (skip consume-time cvt). STF: store tf32-rounded.
template<int PRO, int EPI, int ATF, int BTF, int STF>
__global__ void __launch_bounds__(256) gemm_t(
    const float* __restrict__ A, int lda,
    const float* __restrict__ Bm, int ldb,
    float* __restrict__ C, int ldc, int K,
    const float* __restrict__ bias,
    const float* __restrict__ aux,
    const float* __restrict__ aux2,
    const float* __restrict__ aux3,
    float* __restrict__ part)
{
    constexpr int AW = 36;            // A smem row stride (words), %32=4
    constexpr int BW = 72;            // B smem row stride (words), %32=8
    constexpr int ASZ = 128 * AW;
    constexpr int BSZW = 32 * BW;
    constexpr int NBUF = (PRO == PRO_PLAIN) ? 2 : 1;
    __shared__ uint32_t sm[NBUF * (ASZ + BSZW)];

    const int tid = threadIdx.x;
    const int m0 = blockIdx.y * 128, n0 = blockIdx.x * 64;
    const int wid = tid >> 5, lane = tid & 31;
    const int wm = (wid & 3) * 32;     // warp row offset (4 warps along m)
    const int wn = (wid >> 2) * 32;    // warp col offset (2 warps along n)
    const int qr = lane >> 2;          // 0..7
    const int qc = lane & 3;           // 0..3

    float acc[2][4][4];
#pragma unroll
    for (int h = 0; h < 2; h++)
#pragma unroll
        for (int j = 0; j < 4; j++)
#pragma unroll
            for (int c = 0; c < 4; c++) acc[h][j][c] = 0.f;

    if (PRO == PRO_PLAIN) {
        const uint32_t smb = (uint32_t)__cvta_generic_to_shared(sm);
        auto stage = [&](int k0, int b) {
#pragma unroll
            for (int i = 0; i < 4; i++) {            // A: 128 rows x 32 k
                int slot = tid + 256 * i;
                int row = slot >> 3, k4 = (slot & 7) << 2;
                cp16(smb + (uint32_t)(b * (ASZ + BSZW) + row * AW + k4) * 4,
                     &A[(size_t)(m0 + row) * lda + k0 + k4]);
            }
#pragma unroll
            for (int i = 0; i < 2; i++) {            // B: 32 rows x 64 n
                int slot = tid + 256 * i;
                int row = slot >> 4, n4 = (slot & 15) << 2;
                cp16(smb + (uint32_t)(b * (ASZ + BSZW) + ASZ + row * BW + n4) * 4,
                     &Bm[(size_t)(k0 + row) * ldb + n0 + n4]);
            }
            CP_COMMIT();
        };

        stage(0, 0);
        int buf = 0;
        for (int k0 = 0; k0 < K; k0 += 32) {
            if (k0 + 32 < K) stage(k0 + 32, buf ^ 1);
            if (k0 + 32 < K) { CP_WAIT1(); } else { CP_WAIT0(); }
            __syncthreads();
            const uint32_t* As = sm + buf * (ASZ + BSZW);
            const uint32_t* Bs = As + ASZ;
#pragma unroll
            for (int k8 = 0; k8 < 4; k8++) {
                const int kk = k8 * 8;
                uint32_t a00 = ATF ? As[(wm + qr     ) * AW + kk + qc]     : f2tf_u(As[(wm + qr     ) * AW + kk + qc]);
                uint32_t a01 = ATF ? As[(wm + qr + 8 ) * AW + kk + qc]     : f2tf_u(As[(wm + qr + 8 ) * AW + kk + qc]);
                uint32_t a02 = ATF ? As[(wm + qr     ) * AW + kk + qc + 4] : f2tf_u(As[(wm + qr     ) * AW + kk + qc + 4]);
                uint32_t a03 = ATF ? As[(wm + qr + 8 ) * AW + kk + qc + 4] : f2tf_u(As[(wm + qr + 8 ) * AW + kk + qc + 4]);
                uint32_t a10 = ATF ? As[(wm + qr + 16) * AW + kk + qc]     : f2tf_u(As[(wm + qr + 16) * AW + kk + qc]);
                uint32_t a11 = ATF ? As[(wm + qr + 24) * AW + kk + qc]     : f2tf_u(As[(wm + qr + 24) * AW + kk + qc]);
                uint32_t a12 = ATF ? As[(wm + qr + 16) * AW + kk + qc + 4] : f2tf_u(As[(wm + qr + 16) * AW + kk + qc + 4]);
                uint32_t a13 = ATF ? As[(wm + qr + 24) * AW + kk + qc + 4] : f2tf_u(As[(wm + qr + 24) * AW + kk + qc + 4]);
#pragma unroll
                for (int j = 0; j < 4; j++) {
                    const int cn = wn + j * 8 + qr;
                    uint32_t b0 = BTF ? Bs[(kk + qc    ) * BW + cn] : f2tf_u(Bs[(kk + qc    ) * BW + cn]);
                    uint32_t b1 = BTF ? Bs[(kk + qc + 4) * BW + cn] : f2tf_u(Bs[(kk + qc + 4) * BW + cn]);
                    mma8(acc[0][j], a00, a01, a02, a03, b0, b1);
                    mma8(acc[1][j], a10, a11, a12, a13, b0, b1);
                }
            }
            __syncthreads();
            buf ^= 1;
        }
    } else {
        // synchronous staged path (PRO_ADDRELU)
        uint32_t* As = sm;
        uint32_t* Bs = sm + ASZ;
        const int arow = tid >> 1;
        const int ab   = (tid & 1) * 16;
        const int brow = tid >> 3;
        const int bn   = (tid & 7) * 8;
        for (int k0 = 0; k0 < K; k0 += 32) {
#pragma unroll
            for (int i = 0; i < 4; i++) {
                float4 av = *(const float4*)&A[(size_t)(m0 + arow) * lda + k0 + ab + 4*i];
                const float4 hv = *(const float4*)&aux[(size_t)((m0 + arow) >> 3) * HH + k0 + ab + 4*i];
                av.x = fmaxf(av.x + hv.x, 0.f); av.y = fmaxf(av.y + hv.y, 0.f);
                av.z = fmaxf(av.z + hv.z, 0.f); av.w = fmaxf(av.w + hv.w, 0.f);
                uint4 t;
                t.x = f2tf(av.x); t.y = f2tf(av.y); t.z = f2tf(av.z); t.w = f2tf(av.w);
                *(uint4*)&As[arow * AW + ab + 4*i] = t;
            }
#pragma unroll
            for (int i = 0; i < 2; i++) {
                float4 bv = *(const float4*)&Bm[(size_t)(k0 + brow) * ldb + n0 + bn + 4*i];
                uint4 t;
                t.x = f2tf(bv.x); t.y = f2tf(bv.y); t.z = f2tf(bv.z); t.w = f2tf(bv.w);
                *(uint4*)&Bs[brow * BW + bn + 4*i] = t;
            }
            __syncthreads();
#pragma unroll
            for (int k8 = 0; k8 < 4; k8++) {
                const int kk = k8 * 8;
                uint32_t a00 = As[(wm + qr     ) * AW + kk + qc];
                uint32_t a01 = As[(wm + qr + 8 ) * AW + kk + qc];
                uint32_t a02 = As[(wm + qr     ) * AW + kk + qc + 4];
                uint32_t a03 = As[(wm + qr + 8 ) * AW + kk + qc + 4];
                uint32_t a10 = As[(wm + qr + 16) * AW + kk + qc];
                uint32_t a11 = As[(wm + qr + 24) * AW + kk + qc];
                uint32_t a12 = As[(wm + qr + 16) * AW + kk + qc + 4];
                uint32_t a13 = As[(wm + qr + 24) * AW + kk + qc + 4];
#pragma unroll
                for (int j = 0; j < 4; j++) {
                    const int cn = wn + j * 8 + qr;
                    uint32_t b0 = Bs[(kk + qc    ) * BW + cn];
                    uint32_t b1 = Bs[(kk + qc + 4) * BW + cn];
                    mma8(acc[0][j], a00, a01, a02, a03, b0, b1);
                    mma8(acc[1][j], a10, a11, a12, a13, b0, b1);
                }
            }
            __syncthreads();
        }
    }

    const int mA = m0 + wm + qr;
    const int nB0 = n0 + wn + qc * 2;

    if (EPI <= 3) {
        const bool hasb = (bias != nullptr);
#pragma unroll
        for (int h = 0; h < 2; h++) {
#pragma unroll
            for (int j = 0; j < 4; j++) {
                const int n = nB0 + j * 8;
                const int r0 = mA + h * 16, r1 = r0 + 8;
                float v[4] = {acc[h][j][0], acc[h][j][1], acc[h][j][2], acc[h][j][3]};
                const int mm[4] = {r0, r0, r1, r1};
                const int nn[4] = {n, n + 1, n, n + 1};
#pragma unroll
                for (int c = 0; c < 4; c++) {
                    if (hasb) v[c] += bias[nn[c]];
                    if (EPI == EPI_RELU) v[c] = fmaxf(v[c], 0.f);
                    if (EPI == EPI_EXP)  v[c] = expf(v[c]);
                    if (EPI == EPI_BCASTRELU)
                        v[c] = fmaxf(v[c] + aux[(size_t)(mm[c] >> 3) * HH + nn[c]], 0.f);
                    if (STF) v[c] = __uint_as_float(f2tf(v[c]));
                }
                *(float2*)&C[(size_t)r0 * ldc + n] = make_float2(v[0], v[1]);
                *(float2*)&C[(size_t)r1 * ldc + n] = make_float2(v[2], v[3]);
            }
        }
    } else {
        float s = 0.f;
#pragma unroll
        for (int h = 0; h < 2; h++) {
#pragma unroll
            for (int j = 0; j < 4; j++) {
                const int n = nB0 + j * 8;
                const int r0 = mA + h * 16, r1 = r0 + 8;
                const int mm[4] = {r0, r0, r1, r1};
                const int nn[4] = {n, n + 1, n, n + 1};
#pragma unroll
                for (int c = 0; c < 4; c++) {
                    float v = acc[h][j][c] + bias[nn[c]];
                    if (EPI == EPI_KLD) {
                        float pr = 0.1f * tanhf(v);
                        float e = (pr - aux2[(size_t)mm[c] * ZZ + nn[c]]) /
                                  aux3[(size_t)(mm[c] >> 3) * ZZ + nn[c]];
                        s += e * e;
                    } else { // EPI_RECON
                        float d = aux[(size_t)(mm[c] >> 3) * DD + nn[c]] - v;
                        float nll = 0.5f * (LOG2PI_C + d * d);
                        s += nll * aux2[mm[c] >> 3];
                    }
                }
            }
        }
        __shared__ float red[256];
        red[tid] = s;
        __syncthreads();
        for (int o = 128; o > 0; o >>= 1) {
            if (tid < o) red[tid] += red[tid + o];
            __syncthreads();
        }
        if (tid == 0) part[blockIdx.y * gridDim.x + blockIdx.x] = red[0];
    }
}

// ---------------- persistent scan kernel (tf32, 4 warps, 32x32 tiles) -----
#define SMEM_SCAN ((256*72*2 + 64*260) * 4)

__device__ __forceinline__ void gridbar(unsigned& tgt)
{
    tgt += SCAN_BLOCKS;
    __syncthreads();
    if (threadIdx.x == 0) {
        __threadfence();
        atomicAdd(&g_cnt[(blockIdx.x & 31) << 5], 1u);
    }
    if (threadIdx.x < 32) {
        unsigned s;
        do {
            s = *(volatile unsigned*)&g_cnt[threadIdx.x << 5];
#pragma unroll
            for (int o = 16; o > 0; o >>= 1)
                s += __shfl_xor_sync(0xffffffffu, s, o);
        } while (s < tgt);
        __threadfence();
    }
    __syncthreads();
}

__global__ void __launch_bounds__(SCAN_THREADS, 1) scan_kernel(
    const float* __restrict__ w1z,      // g_w1tf + RR*HH (tf32 bits)
    const float* __restrict__ w2,       // g_drw2tf (tf32 bits)
    const float* __restrict__ b2,       // drift_b2
    const float* __restrict__ noise)
{
    extern __shared__ uint32_t smu[];
    uint32_t* W1s = smu;                     // [256][72]
    uint32_t* W2s = smu + 256*72;            // [256][72]
    uint32_t* St  = smu + 2*256*72;          // [64][260]
    const uint32_t stb = (uint32_t)__cvta_generic_to_shared(St);

    const int tid = threadIdx.x;
    const int bid = blockIdx.x;
    const int wid = tid >> 5, lane = tid & 31;
    const int qr = lane >> 2;   // 0..7
    const int qc = lane & 3;    // 0..3

    const int bmA = bid >> 4;          // 0..7
    const int bnA = bid & 15;          // 0..15
    const int wmA = (wid & 1) * 32;
    const int wnA = (wid >> 1) * 32;

    const int kcB = bid & 3;
    const int moB = (bid >> 2) >> 2;
    const int noB = (bid >> 2) & 3;
    const int wrB = (wid & 1) * 32;
    const int wcB = (wid >> 1) * 32;

    for (int i = tid; i < 256*64; i += SCAN_THREADS) {
        int k = i >> 6, c = i & 63;
        W1s[k*72 + c] = __float_as_uint(w1z[(size_t)k*HH + bnA*64 + c]);
        W2s[k*72 + c] = __float_as_uint(w2[(size_t)(kcB*256 + k)*ZZ + noB*64 + c]);
    }
    __syncthreads();

    unsigned tgt = 0;

    for (int t = 0; t < TT; t++) {
        float* zwt = g_zw + (size_t)t*BSZ*HH;

        // ============ phase A: zw[t] = z_t @ w1z; also emit hid ============
        {
            // stage 64x256 tf32 z tile via cp.async (pre-rounded in g_states_tf)
            const float* ztf = g_states_tf + (size_t)t*BSZ*ZZ;
#pragma unroll
            for (int i = 0; i < 32; i++) {
                int slot = tid + SCAN_THREADS * i;   // 0..4095
                int row = slot >> 6, qw = (slot & 63) << 2;
                cp16(stb + (uint32_t)(row*260 + qw) * 4,
                     &ztf[(size_t)(bmA*64 + row)*ZZ + qw]);
            }
            CP_COMMIT(); CP_WAIT0();
            __syncthreads();

            float acc[2][4][4];
#pragma unroll
            for (int h = 0; h < 2; h++)
#pragma unroll
                for (int j = 0; j < 4; j++)
#pragma unroll
                    for (int c = 0; c < 4; c++) acc[h][j][c] = 0.f;

#pragma unroll 4
            for (int kb = 0; kb < 32; kb++) {
                const int kk = kb * 8;
                uint32_t a00 = St[(wmA + qr     )*260 + kk + qc];
                uint32_t a01 = St[(wmA + qr + 8 )*260 + kk + qc];
                uint32_t a02 = St[(wmA + qr     )*260 + kk + qc + 4];
                uint32_t a03 = St[(wmA + qr + 8 )*260 + kk + qc + 4];
                uint32_t a10 = St[(wmA + qr + 16)*260 + kk + qc];
                uint32_t a11 = St[(wmA + qr + 24)*260 + kk + qc];
                uint32_t a12 = St[(wmA + qr + 16)*260 + kk + qc + 4];
                uint32_t a13 = St[(wmA + qr + 24)*260 + kk + qc + 4];
#pragma unroll
                for (int j = 0; j < 4; j++) {
                    const int n = wnA + j*8 + qr;
                    uint32_t b0 = W1s[(kk + qc    )*72 + n];
                    uint32_t b1 = W1s[(kk + qc + 4)*72 + n];
                    mma8(acc[0][j], a00, a01, a02, a03, b0, b1);
                    mma8(acc[1][j], a10, a11, a12, a13, b0, b1);
                }
            }
            const float* hp = g_hpost + (size_t)t*BB*HH;
            const int mA = bmA*64 + wmA + qr;
#pragma unroll
            for (int h = 0; h < 2; h++) {
#pragma unroll
                for (int j = 0; j < 4; j++) {
                    const int n = bnA*64 + wnA + j*8 + qc*2;
                    const int r0 = mA + h*16, r1 = r0 + 8;
                    *(float2*)&zwt[(size_t)r0*HH + n] = make_float2(acc[h][j][0], acc[h][j][1]);
                    *(float2*)&zwt[(size_t)r1*HH + n] = make_float2(acc[h][j][2], acc[h][j][3]);
                    // hid = tf32(relu(zw + hpost)) — transformed ONCE here
                    float2 h0 = *(const float2*)&hp[(size_t)(r0 >> 3)*HH + n];
                    float2 h1 = *(const float2*)&hp[(size_t)(r1 >> 3)*HH + n];
                    uint2 u0, u1;
                    u0.x = f2tf(fmaxf(acc[h][j][0] + h0.x, 0.f));
                    u0.y = f2tf(fmaxf(acc[h][j][1] + h0.y, 0.f));
                    u1.x = f2tf(fmaxf(acc[h][j][2] + h1.x, 0.f));
                    u1.y = f2tf(fmaxf(acc[h][j][3] + h1.y, 0.f));
                    *(uint2*)&g_hid[(size_t)r0*HH + n] = u0;
                    *(uint2*)&g_hid[(size_t)r1*HH + n] = u1;
                }
            }
        }
        gridbar(tgt);

        // ============ phase B1: partial hid@W2 (tf32 mma, cp.async stage) ============
        {
#pragma unroll
            for (int i = 0; i < 32; i++) {
                int slot = tid + SCAN_THREADS * i;   // 0..4095
                int row = slot >> 6, qw = (slot & 63) << 2;
                cp16(stb + (uint32_t)(row*260 + qw) * 4,
                     &g_hid[(size_t)(moB*64 + row)*HH + kcB*256 + qw]);
            }
            CP_COMMIT(); CP_WAIT0();
            __syncthreads();

            float acc[2][4][4];
#pragma unroll
            for (int h = 0; h < 2; h++)
#pragma unroll
                for (int j = 0; j < 4; j++)
#pragma unroll
                    for (int c = 0; c < 4; c++) acc[h][j][c] = 0.f;

#pragma unroll 4
            for (int kb = 0; kb < 32; kb++) {
                const int kk = kb * 8;
                uint32_t a00 = St[(wrB + qr     )*260 + kk + qc];
                uint32_t a01 = St[(wrB + qr + 8 )*260 + kk + qc];
                uint32_t a02 = St[(wrB + qr     )*260 + kk + qc + 4];
                uint32_t a03 = St[(wrB + qr + 8 )*260 + kk + qc + 4];
                uint32_t a10 = St[(wrB + qr + 16)*260 + kk + qc];
                uint32_t a11 = St[(wrB + qr + 24)*260 + kk + qc];
                uint32_t a12 = St[(wrB + qr + 16)*260 + kk + qc + 4];
                uint32_t a13 = St[(wrB + qr + 24)*260 + kk + qc + 4];
#pragma unroll
                for (int j = 0; j < 4; j++) {
                    const int n = wcB + j*8 + qr;
                    uint32_t b0 = W2s[(kk + qc    )*72 + n];
                    uint32_t b1 = W2s[(kk + qc + 4)*72 + n];
                    mma8(acc[0][j], a00, a01, a02, a03, b0, b1);
                    mma8(acc[1][j], a10, a11, a12, a13, b0, b1);
                }
            }
            float* gp = g_part + (size_t)kcB*BSZ*ZZ;
            const int mB = moB*64 + wrB + qr;
#pragma unroll
            for (int h = 0; h < 2; h++) {
#pragma unroll
                for (int j = 0; j < 4; j++) {
                    const int n = noB*64 + wcB + j*8 + qc*2;
                    const int r0 = mB + h*16;
                    *(float2*)&gp[(size_t)r0*ZZ + n]     = make_float2(acc[h][j][0], acc[h][j][1]);
                    *(float2*)&gp[(size_t)(r0+8)*ZZ + n] = make_float2(acc[h][j][2], acc[h][j][3]);
                }
            }
        }
        gridbar(tgt);

        // ============ phase B2: combine + tanh + Euler + row minmax (fp32) ============
        {
            const int row = bid*4 + wid;
            const float* zr = g_states + (size_t)t*BSZ*ZZ + (size_t)row*ZZ;
            const float* nr = noise + (size_t)t*BSZ*ZZ + (size_t)row*ZZ;
            const float* dr = g_diff + ((size_t)t*BB + (row >> 3))*ZZ;
            float* pr = g_post + (size_t)t*BSZ*ZZ + (size_t)row*ZZ;
            float* outz = g_states + (size_t)(t+1)*BSZ*ZZ + (size_t)row*ZZ;
            float* outztf = g_states_tf + (size_t)(t+1)*BSZ*ZZ + (size_t)row*ZZ;

            float v8[8];
            float vmin = 3.4e38f, vmax = -3.4e38f;
#pragma unroll
            for (int j = 0; j < 2; j++) {
                const int cb = lane*4 + 128*j;
                float4 s  = *(const float4*)&g_part[0*BSZ*ZZ + (size_t)row*ZZ + cb];
                float4 s1 = *(const float4*)&g_part[1*BSZ*ZZ + (size_t)row*ZZ + cb];
                float4 s2 = *(const float4*)&g_part[2*BSZ*ZZ + (size_t)row*ZZ + cb];
                float4 s3 = *(const float4*)&g_part[3*BSZ*ZZ + (size_t)row*ZZ + cb];
                float4 bb = *(const float4*)&b2[cb];
                float4 zv = *(const float4*)&zr[cb];
                float4 nv = *(const float4*)&nr[cb];
                float4 dv = *(const float4*)&dr[cb];
                float pd0 = 0.1f * tanhf(s.x + s1.x + s2.x + s3.x + bb.x);
                float pd1 = 0.1f * tanhf(s.y + s1.y + s2.y + s3.y + bb.y);
                float pd2 = 0.1f * tanhf(s.z + s1.z + s2.z + s3.z + bb.z);
                float pd3 = 0.1f * tanhf(s.w + s1.w + s2.w + s3.w + bb.w);
                *(float4*)&pr[cb] = make_float4(pd0, pd1, pd2, pd3);
                float n0v = zv.x + DT_C*pd0 + SQRT_DT_C*dv.x*nv.x;
                float n1v = zv.y + DT_C*pd1 + SQRT_DT_C*dv.y*nv.y;
                float n2v = zv.z + DT_C*pd2 + SQRT_DT_C*dv.z*nv.z;
                float n3v = zv.w + DT_C*pd3 + SQRT_DT_C*dv.w*nv.w;
                v8[j*4+0] = n0v; v8[j*4+1] = n1v; v8[j*4+2] = n2v; v8[j*4+3] = n3v;
                vmin = fminf(vmin, fminf(fminf(n0v, n1v), fminf(n2v, n3v)));
                vmax = fmaxf(vmax, fmaxf(fmaxf(n0v, n1v), fmaxf(n2v, n3v)));
            }
#pragma unroll
            for (int o = 16; o > 0; o >>= 1) {
                vmin = fminf(vmin, __shfl_xor_sync(0xffffffffu, vmin, o));
                vmax = fmaxf(vmax, __shfl_xor_sync(0xffffffffu, vmax, o));
            }
            const float inv = 1.f / (vmax - vmin);
#pragma unroll
            for (int j = 0; j < 2; j++) {
                const int cb = lane*4 + 128*j;
                float z0v = (v8[j*4+0]-vmin)*inv, z1v = (v8[j*4+1]-vmin)*inv;
                float z2v = (v8[j*4+2]-vmin)*inv, z3v = (v8[j*4+3]-vmin)*inv;
                *(float4*)&outz[cb] = make_float4(z0v, z1v, z2v, z3v);
                uint4 u;
                u.x = f2tf(z0v); u.y = f2tf(z1v); u.z = f2tf(z2v); u.w = f2tf(z3v);
                *(uint4*)&outztf[cb] = u;
            }
        }
        gridbar(tgt);
    }
}

// ---------------- weight/activation tf32 pre-conversion (+barrier reset) --
__global__ void convw_kernel(const float* __restrict__ dw1,
                             const float* __restrict__ pw1,
                             const float* __restrict__ dif1,
                             const float* __restrict__ dif2,
                             const float* __restrict__ drw2,
                             const float* __restrict__ pw2,
                             const float* __restrict__ ph,
                             const float* __restrict__ php)
{
    if (blockIdx.x == 0 && threadIdx.x < 32) g_cnt[threadIdx.x << 5] = 0u;
    const long N1 = (long)(RR+ZZ)*HH;
    const long N3 = (long)RR*HH;
    const long N4 = (long)HH*ZZ;
    const long N5 = (long)HH*DD;
    const long N6 = (long)TT*BB*RR;
    const long total = 2*N1 + N3 + 2*N4 + N5 + 2*N6;
    for (long i = (long)blockIdx.x*blockDim.x + threadIdx.x; i < total;
         i += (long)gridDim.x*blockDim.x) {
        long j = i;
        if (j < N1) { g_w1tf[j]  = __uint_as_float(f2tf(dw1[j]));  continue; }
        j -= N1;
        if (j < N1) { g_pw1tf[j] = __uint_as_float(f2tf(pw1[j]));  continue; }
        j -= N1;
        if (j < N3) { g_dw1tf[j] = __uint_as_float(f2tf(dif1[j])); continue; }
        j -= N3;
        if (j < N4) { g_dfw2tf[j] = __uint_as_float(f2tf(dif2[j])); continue; }
        j -= N4;
        if (j < N4) { g_drw2tf[j] = __uint_as_float(f2tf(drw2[j])); continue; }
        j -= N4;
        if (j < N5) { g_pw2tf[j] = __uint_as_float(f2tf(pw2[j]));  continue; }
        j -= N5;
        if (j < N6) { g_phtf[j]  = __uint_as_float(f2tf(ph[j]));   continue; }
        j -= N6;
        g_hptf[j] = __uint_as_float(f2tf(php[j]));
    }
}

// ---------------- small kernels ----------------
__global__ void mt_kernel(const float* __restrict__ M)
{
    int r = blockIdx.x * blockDim.x + threadIdx.x;
    if (r < TT * BB) {
        const float* p = M + (size_t)r * DD;
        float s = 0.f;
        for (int d = 0; d < DD; d++) s += p[d];
        g_Mt[r] = s * (1.f / DD);
    }
}

__global__ void z0_kernel(const float* __restrict__ cov,
                          const float* __restrict__ w1, const float* __restrict__ b1,
                          const float* __restrict__ w2, const float* __restrict__ b2)
{
    int b = blockIdx.x;
    __shared__ float cv[16];
    __shared__ float hid[64];
    if (threadIdx.x < 16) cv[threadIdx.x] = cov[b * 16 + threadIdx.x];
    __syncthreads();
    if (threadIdx.x < 64) {
        float s = b1[threadIdx.x];
        for (int i = 0; i < 16; i++) s += cv[i] * w1[i * 64 + threadIdx.x];
        hid[threadIdx.x] = fmaxf(s, 0.f);
    }
    __syncthreads();
    int n = threadIdx.x;
    float s = b2[n];
    for (int j = 0; j < 64; j++) s += hid[j] * w2[j * 256 + n];
    float z = tanhf(s);
    for (int ss = 0; ss < SS; ss++) {
        g_states[(size_t)(b * SS + ss) * ZZ + n] = z;
        g_states_tf[(size_t)(b * SS + ss) * ZZ + n] = __uint_as_float(f2tf(z));
    }
}

__global__ void out_copy_kernel(float* __restrict__ out)
{
    int i = blockIdx.x * 256 + threadIdx.x;
    out[i] = g_states[(size_t)TT * BSZ * ZZ + i];
}

__global__ void scal_kernel(float* __restrict__ out)
{
    __shared__ float red[256];
    int tid = threadIdx.x;
    float s = 0.f;
    for (int i = tid; i < KLD_PARTS; i += 256) s += g_kld_part[i];
    red[tid] = s;
    __syncthreads();
    for (int o = 128; o > 0; o >>= 1) { if (tid < o) red[tid] += red[tid + o]; __syncthreads(); }
    float kldsum = red[0];
    __syncthreads();
    s = 0.f;
    for (int i = tid; i < RECON_PARTS; i += 256) s += g_recon_part[i];
    red[tid] = s;
    __syncthreads();
    for (int o = 128; o > 0; o >>= 1) { if (tid < o) red[tid] += red[tid + o]; __syncthreads(); }
    if (tid == 0) {
        float reconsum = red[0];
        float lk = (0.5f * DT_C / (float)(BB * SS)) * kldsum;
        float lr = reconsum * (1.f / (float)(BB * SS));
        out[131072] = lr + lk;   // loss_total
        out[131073] = lr;        // loss_recon
        out[131074] = lk;        // loss_kld
    }
}

// ---------------- launch ----------------
extern "C" void kernel_launch(void* const* d_in, const int* in_sizes, int n_in,
                              void* d_out, int out_size)
{
    (void)in_sizes; (void)n_in; (void)out_size;
    const float* X        = (const float*)d_in[0];
    const float* M        = (const float*)d_in[1];
    const float* cov      = (const float*)d_in[2];
    const float* path_h   = (const float*)d_in[3];
    const float* path_hpos= (const float*)d_in[4];
    const float* noise    = (const float*)d_in[5];
    const float* drift_w1 = (const float*)d_in[6];
    const float* drift_b1 = (const float*)d_in[7];
    const float* drift_w2 = (const float*)d_in[8];
    const float* drift_b2 = (const float*)d_in[9];
    const float* diff_w1  = (const float*)d_in[10];
    const float* diff_b1  = (const float*)d_in[11];
    const float* diff_w2  = (const float*)d_in[12];
    const float* diff_b2  = (const float*)d_in[13];
    const float* p_w1     = (const float*)d_in[14];
    const float* p_b1     = (const float*)d_in[15];
    const float* p_w2     = (const float*)d_in[16];
    const float* p_b2     = (const float*)d_in[17];
    const float* cov_w1   = (const float*)d_in[18];
    const float* cov_b1   = (const float*)d_in[19];
    const float* cov_w2   = (const float*)d_in[20];
    const float* cov_b2   = (const float*)d_in[21];
    float* out = (float*)d_out;

    float *hprior, *hpost, *ppart, *dtmp, *diffp, *states, *zw, *post, *A3, *kldp, *reconp, *Mtp;
    float *w1tf, *pw1tf, *dw1tf, *dfw2tf, *drw2tf, *pw2tf, *phtf, *hptf;
    cudaGetSymbolAddress((void**)&hprior, g_hprior);
    cudaGetSymbolAddress((void**)&hpost,  g_hpost);
    cudaGetSymbolAddress((void**)&ppart,  g_ppart);
    cudaGetSymbolAddress((void**)&dtmp,   g_dtmp);
    cudaGetSymbolAddress((void**)&diffp,  g_diff);
    cudaGetSymbolAddress((void**)&states, g_states);
    cudaGetSymbolAddress((void**)&zw,     g_zw);
    cudaGetSymbolAddress((void**)&post,   g_post);
    cudaGetSymbolAddress((void**)&A3,     g_A3);
    cudaGetSymbolAddress((void**)&kldp,   g_kld_part);
    cudaGetSymbolAddress((void**)&reconp, g_recon_part);
    cudaGetSymbolAddress((void**)&Mtp,    g_Mt);
    cudaGetSymbolAddress((void**)&w1tf,   g_w1tf);
    cudaGetSymbolAddress((void**)&pw1tf,  g_pw1tf);
    cudaGetSymbolAddress((void**)&dw1tf,  g_dw1tf);
    cudaGetSymbolAddress((void**)&dfw2tf, g_dfw2tf);
    cudaGetSymbolAddress((void**)&drw2tf, g_drw2tf);
    cudaGetSymbolAddress((void**)&pw2tf,  g_pw2tf);
    cudaGetSymbolAddress((void**)&phtf,   g_phtf);
    cudaGetSymbolAddress((void**)&hptf,   g_hptf);

    static int smem_set = 0;
    if (!smem_set) {
        cudaFuncSetAttribute(scan_kernel,
                             cudaFuncAttributeMaxDynamicSharedMemorySize, SMEM_SCAN);
        smem_set = 1;
    }

    // tf32 pre-conversion + barrier reset
    convw_kernel<<<4096, 256>>>(drift_w1, p_w1, diff_w1, diff_w2, drift_w2, p_w2,
                                path_h, path_hpos);
    // hpost (needed by scan)
    gemm_t<PRO_PLAIN, EPI_STORE, 1, 1, 0><<<dim3(16, 100), 256>>>(
        hptf, RR, w1tf, HH, hpost, HH, RR, drift_b1,
        nullptr, nullptr, nullptr, nullptr);
    // dtmp (tf32-rounded store)
    gemm_t<PRO_PLAIN, EPI_RELU, 1, 1, 1><<<dim3(16, 100), 256>>>(
        phtf, RR, dw1tf, HH, dtmp, HH, RR, diff_b1,
        nullptr, nullptr, nullptr, nullptr);
    // diffusion (needed by scan)
    gemm_t<PRO_PLAIN, EPI_EXP, 1, 1, 0><<<dim3(4, 100), 256>>>(
        dtmp, HH, dfw2tf, ZZ, diffp, ZZ, HH, diff_b2,
        nullptr, nullptr, nullptr, nullptr);
    // z0
    z0_kernel<<<BB, 256>>>(cov, cov_w1, cov_b1, cov_w2, cov_b2);
    // persistent scan
    scan_kernel<<<SCAN_BLOCKS, SCAN_THREADS, SMEM_SCAN>>>(
        w1tf + (size_t)RR * HH, drw2tf, drift_b2, noise);

    // batch epilogue
    gemm_t<PRO_PLAIN, EPI_STORE, 1, 1, 0><<<dim3(16, 100), 256>>>(
        phtf, RR, w1tf, HH, hprior, HH, RR, drift_b1,
        nullptr, nullptr, nullptr, nullptr);
    gemm_t<PRO_PLAIN, EPI_STORE, 1, 1, 0><<<dim3(16, 100), 256>>>(
        phtf, RR, pw1tf, HH, ppart, HH, RR, p_b1,
        nullptr, nullptr, nullptr, nullptr);
    mt_kernel<<<(TT * BB + 255) / 256, 256>>>(M);
    gemm_t<PRO_ADDRELU, EPI_KLD, 0, 0, 0><<<dim3(4, 800), 256>>>(
        zw, HH, drift_w2, ZZ, nullptr, 0, HH, drift_b2,
        hprior, post, diffp, kldp);
    gemm_t<PRO_PLAIN, EPI_BCASTRELU, 0, 1, 1><<<dim3(16, 800), 256>>>(
        states + (size_t)BSZ * ZZ, ZZ, pw1tf + (size_t)RR * HH, HH,
        A3, HH, ZZ, nullptr, ppart, nullptr, nullptr, nullptr);
    gemm_t<PRO_PLAIN, EPI_RECON, 1, 1, 0><<<dim3(2, 800), 256>>>(
        A3, HH, pw2tf, DD, nullptr, 0, HH, p_b2,
        X, Mtp, nullptr, reconp);

    // output: z_final then (total, recon, kld)
    out_copy_kernel<<<512, 256>>>(out);
    scal_kernel<<<1, 256>>>(out);
}

// round 15
// speedup vs baseline: 1.5191x; 1.0277x over previous
#include <cuda_runtime.h>
#include <math.h>
#include <stdint.h>

#define TT 200
#define BB 64
#define SS 8
#define DD 128
#define RR 512
#define ZZ 256
#define HH 1024
#define BSZ (BB*SS)            /* 512 rows per step */
#define DT_C 0.05f
#define SQRT_DT_C 0.223606797749979f
#define LOG2PI_C 1.8378770664093453f

#define KLD_PARTS  (800*4)
#define RECON_PARTS (800*2)

#define SCAN_BLOCKS 128
#define SCAN_THREADS 128

// ---------------- device scratch (static, allocation-free) ----------------
__device__ float g_hprior[TT*BB*HH];        // h@drift_w1[:R] + b1
__device__ float g_hpost [TT*BB*HH];        // hpos@drift_w1[:R] + b1
__device__ float g_ppart [TT*BB*HH];        // h@p_w1[:R] + p_b1
__device__ float g_dtmp  [TT*BB*HH];        // relu(h@diff_w1+b1), tf32-rounded
__device__ float g_diff  [TT*BB*ZZ];        // exp(diff MLP)
__device__ float g_Mt    [TT*BB];
__device__ float g_states[(TT+1)*BSZ*ZZ];   // z trajectory (normalized, fp32)
__device__ float g_states_tf[(TT+1)*BSZ*ZZ];// z trajectory tf32-rounded bits
__device__ float g_zw    [TT*BSZ*HH];       // z_t @ drift_w1[R:] (raw fp32, for KLD)
__device__ float g_hid   [BSZ*HH];          // tf32 relu(zw+hpost), current step
__device__ float g_post  [TT*BSZ*ZZ];       // posterior drift
__device__ float g_A3    [TT*BSZ*HH];       // decoder hidden, tf32-rounded
__device__ float g_part  [4*BSZ*ZZ];        // split-K partials for scan
__device__ float g_kld_part[KLD_PARTS];
__device__ float g_recon_part[RECON_PARTS];
__device__ unsigned g_cnt[32*32];           // per-group barrier counters (128B apart)

// tf32 pre-converted copies (rounded-to-nearest once; bit-identical downstream)
__device__ float g_w1tf [(RR+ZZ)*HH];       // drift_w1
__device__ float g_pw1tf[(RR+ZZ)*HH];       // p_w1
__device__ float g_dw1tf[RR*HH];            // diff_w1
__device__ float g_dfw2tf[HH*ZZ];           // diff_w2
__device__ float g_drw2tf[HH*ZZ];           // drift_w2
__device__ float g_pw2tf[HH*DD];            // p_w2
__device__ float g_phtf [TT*BB*RR];         // path_h
__device__ float g_hptf [TT*BB*RR];         // path_hpos

// ---------------- tf32 / async helpers ----------------
__device__ __forceinline__ uint32_t f2tf(float f)
{
    uint32_t u;
    asm("cvt.rna.tf32.f32 %0, %1;" : "=r"(u) : "f"(f));
    return u;
}

__device__ __forceinline__ uint32_t f2tf_u(uint32_t raw)
{
    return f2tf(__uint_as_float(raw));
}

__device__ __forceinline__ void mma8(float* c,
    uint32_t a0, uint32_t a1, uint32_t a2, uint32_t a3,
    uint32_t b0, uint32_t b1)
{
    asm("mma.sync.aligned.m16n8k8.row.col.f32.tf32.tf32.f32 "
        "{%0,%1,%2,%3},{%4,%5,%6,%7},{%8,%9},{%0,%1,%2,%3};"
        : "+f"(c[0]), "+f"(c[1]), "+f"(c[2]), "+f"(c[3])
        : "r"(a0), "r"(a1), "r"(a2), "r"(a3), "r"(b0), "r"(b1));
}

__device__ __forceinline__ void cp16(uint32_t smem_dst, const void* gsrc)
{
    asm volatile("cp.async.cg.shared.global [%0], [%1], 16;\n"
                 :: "r"(smem_dst), "l"(gsrc));
}
#define CP_COMMIT() asm volatile("cp.async.commit_group;\n" ::: "memory")
#define CP_WAIT1()  asm volatile("cp.async.wait_group 1;\n" ::: "memory")
#define CP_WAIT0()  asm volatile("cp.async.wait_group 0;\n" ::: "memory")

// ---------------- generic 128x64 tf32 GEMM with fused pro/epilogues ------
#define PRO_PLAIN 0
#define PRO_ADDRELU 1      // A := relu(A + aux[(m>>3)*H + k])
#define EPI_STORE 0        // C = acc (+bias)
#define EPI_RELU  1
#define EPI_EXP   2
#define EPI_BCASTRELU 3    // C = relu(acc + aux[(m>>3)*H + n])
#define EPI_KLD   4        // reduce ((0.1 tanh(acc+b)-post)/diff)^2
#define EPI_RECON 5        // reduce 0.5(log2pi+(X-(acc+b))^2)*Mt

// ATF/BTF: A/B already tf32-rounded (skip consume-time cvt). STF: store tf32-rounded.
template<int PRO, int EPI, int ATF, int BTF, int STF>
__global__ void __launch_bounds__(256) gemm_t(
    const float* __restrict__ A, int lda,
    const float* __restrict__ Bm, int ldb,
    float* __restrict__ C, int ldc, int K,
    const float* __restrict__ bias,
    const float* __restrict__ aux,
    const float* __restrict__ aux2,
    const float* __restrict__ aux3,
    float* __restrict__ part)
{
    constexpr int AW = 36;            // A smem row stride (words), %32=4
    constexpr int BW = 72;            // B smem row stride (words), %32=8
    constexpr int ASZ = 128 * AW;
    constexpr int BSZW = 32 * BW;
    constexpr int NBUF = (PRO == PRO_PLAIN) ? 2 : 1;
    __shared__ uint32_t sm[NBUF * (ASZ + BSZW)];

    const int tid = threadIdx.x;
    const int m0 = blockIdx.y * 128, n0 = blockIdx.x * 64;
    const int wid = tid >> 5, lane = tid & 31;
    const int wm = (wid & 3) * 32;     // warp row offset (4 warps along m)
    const int wn = (wid >> 2) * 32;    // warp col offset (2 warps along n)
    const int qr = lane >> 2;          // 0..7
    const int qc = lane & 3;           // 0..3

    float acc[2][4][4];
#pragma unroll
    for (int h = 0; h < 2; h++)
#pragma unroll
        for (int j = 0; j < 4; j++)
#pragma unroll
            for (int c = 0; c < 4; c++) acc[h][j][c] = 0.f;

    if (PRO == PRO_PLAIN) {
        const uint32_t smb = (uint32_t)__cvta_generic_to_shared(sm);
        auto stage = [&](int k0, int b) {
#pragma unroll
            for (int i = 0; i < 4; i++) {            // A: 128 rows x 32 k
                int slot = tid + 256 * i;
                int row = slot >> 3, k4 = (slot & 7) << 2;
                cp16(smb + (uint32_t)(b * (ASZ + BSZW) + row * AW + k4) * 4,
                     &A[(size_t)(m0 + row) * lda + k0 + k4]);
            }
#pragma unroll
            for (int i = 0; i < 2; i++) {            // B: 32 rows x 64 n
                int slot = tid + 256 * i;
                int row = slot >> 4, n4 = (slot & 15) << 2;
                cp16(smb + (uint32_t)(b * (ASZ + BSZW) + ASZ + row * BW + n4) * 4,
                     &Bm[(size_t)(k0 + row) * ldb + n0 + n4]);
            }
            CP_COMMIT();
        };

        stage(0, 0);
        int buf = 0;
        for (int k0 = 0; k0 < K; k0 += 32) {
            if (k0 + 32 < K) stage(k0 + 32, buf ^ 1);
            if (k0 + 32 < K) { CP_WAIT1(); } else { CP_WAIT0(); }
            __syncthreads();
            const uint32_t* As = sm + buf * (ASZ + BSZW);
            const uint32_t* Bs = As + ASZ;
#pragma unroll
            for (int k8 = 0; k8 < 4; k8++) {
                const int kk = k8 * 8;
                uint32_t a00 = ATF ? As[(wm + qr     ) * AW + kk + qc]     : f2tf_u(As[(wm + qr     ) * AW + kk + qc]);
                uint32_t a01 = ATF ? As[(wm + qr + 8 ) * AW + kk + qc]     : f2tf_u(As[(wm + qr + 8 ) * AW + kk + qc]);
                uint32_t a02 = ATF ? As[(wm + qr     ) * AW + kk + qc + 4] : f2tf_u(As[(wm + qr     ) * AW + kk + qc + 4]);
                uint32_t a03 = ATF ? As[(wm + qr + 8 ) * AW + kk + qc + 4] : f2tf_u(As[(wm + qr + 8 ) * AW + kk + qc + 4]);
                uint32_t a10 = ATF ? As[(wm + qr + 16) * AW + kk + qc]     : f2tf_u(As[(wm + qr + 16) * AW + kk + qc]);
                uint32_t a11 = ATF ? As[(wm + qr + 24) * AW + kk + qc]     : f2tf_u(As[(wm + qr + 24) * AW + kk + qc]);
                uint32_t a12 = ATF ? As[(wm + qr + 16) * AW + kk + qc + 4] : f2tf_u(As[(wm + qr + 16) * AW + kk + qc + 4]);
                uint32_t a13 = ATF ? As[(wm + qr + 24) * AW + kk + qc + 4] : f2tf_u(As[(wm + qr + 24) * AW + kk + qc + 4]);
#pragma unroll
                for (int j = 0; j < 4; j++) {
                    const int cn = wn + j * 8 + qr;
                    uint32_t b0 = BTF ? Bs[(kk + qc    ) * BW + cn] : f2tf_u(Bs[(kk + qc    ) * BW + cn]);
                    uint32_t b1 = BTF ? Bs[(kk + qc + 4) * BW + cn] : f2tf_u(Bs[(kk + qc + 4) * BW + cn]);
                    mma8(acc[0][j], a00, a01, a02, a03, b0, b1);
                    mma8(acc[1][j], a10, a11, a12, a13, b0, b1);
                }
            }
            __syncthreads();
            buf ^= 1;
        }
    } else {
        // synchronous staged path (PRO_ADDRELU)
        uint32_t* As = sm;
        uint32_t* Bs = sm + ASZ;
        const int arow = tid >> 1;
        const int ab   = (tid & 1) * 16;
        const int brow = tid >> 3;
        const int bn   = (tid & 7) * 8;
        for (int k0 = 0; k0 < K; k0 += 32) {
#pragma unroll
            for (int i = 0; i < 4; i++) {
                float4 av = *(const float4*)&A[(size_t)(m0 + arow) * lda + k0 + ab + 4*i];
                const float4 hv = *(const float4*)&aux[(size_t)((m0 + arow) >> 3) * HH + k0 + ab + 4*i];
                av.x = fmaxf(av.x + hv.x, 0.f); av.y = fmaxf(av.y + hv.y, 0.f);
                av.z = fmaxf(av.z + hv.z, 0.f); av.w = fmaxf(av.w + hv.w, 0.f);
                uint4 t;
                t.x = f2tf(av.x); t.y = f2tf(av.y); t.z = f2tf(av.z); t.w = f2tf(av.w);
                *(uint4*)&As[arow * AW + ab + 4*i] = t;
            }
#pragma unroll
            for (int i = 0; i < 2; i++) {
                float4 bv = *(const float4*)&Bm[(size_t)(k0 + brow) * ldb + n0 + bn + 4*i];
                uint4 t;
                t.x = f2tf(bv.x); t.y = f2tf(bv.y); t.z = f2tf(bv.z); t.w = f2tf(bv.w);
                *(uint4*)&Bs[brow * BW + bn + 4*i] = t;
            }
            __syncthreads();
#pragma unroll
            for (int k8 = 0; k8 < 4; k8++) {
                const int kk = k8 * 8;
                uint32_t a00 = As[(wm + qr     ) * AW + kk + qc];
                uint32_t a01 = As[(wm + qr + 8 ) * AW + kk + qc];
                uint32_t a02 = As[(wm + qr     ) * AW + kk + qc + 4];
                uint32_t a03 = As[(wm + qr + 8 ) * AW + kk + qc + 4];
                uint32_t a10 = As[(wm + qr + 16) * AW + kk + qc];
                uint32_t a11 = As[(wm + qr + 24) * AW + kk + qc];
                uint32_t a12 = As[(wm + qr + 16) * AW + kk + qc + 4];
                uint32_t a13 = As[(wm + qr + 24) * AW + kk + qc + 4];
#pragma unroll
                for (int j = 0; j < 4; j++) {
                    const int cn = wn + j * 8 + qr;
                    uint32_t b0 = Bs[(kk + qc    ) * BW + cn];
                    uint32_t b1 = Bs[(kk + qc + 4) * BW + cn];
                    mma8(acc[0][j], a00, a01, a02, a03, b0, b1);
                    mma8(acc[1][j], a10, a11, a12, a13, b0, b1);
                }
            }
            __syncthreads();
        }
    }

    const int mA = m0 + wm + qr;
    const int nB0 = n0 + wn + qc * 2;

    if (EPI <= 3) {
        const bool hasb = (bias != nullptr);
#pragma unroll
        for (int h = 0; h < 2; h++) {
#pragma unroll
            for (int j = 0; j < 4; j++) {
                const int n = nB0 + j * 8;
                const int r0 = mA + h * 16, r1 = r0 + 8;
                float v[4] = {acc[h][j][0], acc[h][j][1], acc[h][j][2], acc[h][j][3]};
                const int mm[4] = {r0, r0, r1, r1};
                const int nn[4] = {n, n + 1, n, n + 1};
#pragma unroll
                for (int c = 0; c < 4; c++) {
                    if (hasb) v[c] += bias[nn[c]];
                    if (EPI == EPI_RELU) v[c] = fmaxf(v[c], 0.f);
                    if (EPI == EPI_EXP)  v[c] = expf(v[c]);
                    if (EPI == EPI_BCASTRELU)
                        v[c] = fmaxf(v[c] + aux[(size_t)(mm[c] >> 3) * HH + nn[c]], 0.f);
                    if (STF) v[c] = __uint_as_float(f2tf(v[c]));
                }
                *(float2*)&C[(size_t)r0 * ldc + n] = make_float2(v[0], v[1]);
                *(float2*)&C[(size_t)r1 * ldc + n] = make_float2(v[2], v[3]);
            }
        }
    } else {
        float s = 0.f;
#pragma unroll
        for (int h = 0; h < 2; h++) {
#pragma unroll
            for (int j = 0; j < 4; j++) {
                const int n = nB0 + j * 8;
                const int r0 = mA + h * 16, r1 = r0 + 8;
                const int mm[4] = {r0, r0, r1, r1};
                const int nn[4] = {n, n + 1, n, n + 1};
#pragma unroll
                for (int c = 0; c < 4; c++) {
                    float v = acc[h][j][c] + bias[nn[c]];
                    if (EPI == EPI_KLD) {
                        float pr = 0.1f * tanhf(v);
                        float e = (pr - aux2[(size_t)mm[c] * ZZ + nn[c]]) /
                                  aux3[(size_t)(mm[c] >> 3) * ZZ + nn[c]];
                        s += e * e;
                    } else { // EPI_RECON
                        float d = aux[(size_t)(mm[c] >> 3) * DD + nn[c]] - v;
                        float nll = 0.5f * (LOG2PI_C + d * d);
                        s += nll * aux2[mm[c] >> 3];
                    }
                }
            }
        }
        __shared__ float red[256];
        red[tid] = s;
        __syncthreads();
        for (int o = 128; o > 0; o >>= 1) {
            if (tid < o) red[tid] += red[tid + o];
            __syncthreads();
        }
        if (tid == 0) part[blockIdx.y * gridDim.x + blockIdx.x] = red[0];
    }
}

// ---------------- persistent scan kernel (tf32, 4 warps, 32x32 tiles) -----
// 8 independent row-groups of 16 blocks; barriers are group-scoped.
#define SMEM_SCAN ((256*72*2 + 64*260) * 4)

__device__ __forceinline__ void gbar(unsigned& tgt, int g)
{
    tgt += 16;
    __syncthreads();
    if (threadIdx.x == 0) {
        __threadfence();
        atomicAdd(&g_cnt[g << 5], 1u);
        while (*(volatile unsigned*)&g_cnt[g << 5] < tgt) { }
        __threadfence();
    }
    __syncthreads();
}

__global__ void __launch_bounds__(SCAN_THREADS, 1) scan_kernel(
    const float* __restrict__ w1z,      // g_w1tf + RR*HH (tf32 bits)
    const float* __restrict__ w2,       // g_drw2tf (tf32 bits)
    const float* __restrict__ b2,       // drift_b2
    const float* __restrict__ noise)
{
    extern __shared__ uint32_t smu[];
    uint32_t* W1s = smu;                     // [256][72]
    uint32_t* W2s = smu + 256*72;            // [256][72]
    uint32_t* St  = smu + 2*256*72;          // [64][260]
    const uint32_t stb = (uint32_t)__cvta_generic_to_shared(St);

    const int tid = threadIdx.x;
    const int bid = blockIdx.x;
    const int grp = bid >> 4;          // row-group 0..7 (rows grp*64..grp*64+63)
    const int wid = tid >> 5, lane = tid & 31;
    const int qr = lane >> 2;   // 0..7
    const int qc = lane & 3;    // 0..3

    const int bmA = bid >> 4;          // == grp
    const int bnA = bid & 15;          // 0..15
    const int wmA = (wid & 1) * 32;
    const int wnA = (wid >> 1) * 32;

    const int kcB = bid & 3;
    const int moB = (bid >> 2) >> 2;   // == grp
    const int noB = (bid >> 2) & 3;
    const int wrB = (wid & 1) * 32;
    const int wcB = (wid >> 1) * 32;

    for (int i = tid; i < 256*64; i += SCAN_THREADS) {
        int k = i >> 6, c = i & 63;
        W1s[k*72 + c] = __float_as_uint(w1z[(size_t)k*HH + bnA*64 + c]);
        W2s[k*72 + c] = __float_as_uint(w2[(size_t)(kcB*256 + k)*ZZ + noB*64 + c]);
    }
    __syncthreads();

    unsigned tgt = 0;

    for (int t = 0; t < TT; t++) {
        float* zwt = g_zw + (size_t)t*BSZ*HH;

        // ============ phase A: zw[t] = z_t @ w1z; also emit hid ============
        {
            // stage 64x256 tf32 z tile via cp.async (pre-rounded in g_states_tf)
            const float* ztf = g_states_tf + (size_t)t*BSZ*ZZ;
#pragma unroll
            for (int i = 0; i < 32; i++) {
                int slot = tid + SCAN_THREADS * i;   // 0..4095
                int row = slot >> 6, qw = (slot & 63) << 2;
                cp16(stb + (uint32_t)(row*260 + qw) * 4,
                     &ztf[(size_t)(bmA*64 + row)*ZZ + qw]);
            }
            CP_COMMIT(); CP_WAIT0();
            __syncthreads();

            float acc[2][4][4];
#pragma unroll
            for (int h = 0; h < 2; h++)
#pragma unroll
                for (int j = 0; j < 4; j++)
#pragma unroll
                    for (int c = 0; c < 4; c++) acc[h][j][c] = 0.f;

#pragma unroll 4
            for (int kb = 0; kb < 32; kb++) {
                const int kk = kb * 8;
                uint32_t a00 = St[(wmA + qr     )*260 + kk + qc];
                uint32_t a01 = St[(wmA + qr + 8 )*260 + kk + qc];
                uint32_t a02 = St[(wmA + qr     )*260 + kk + qc + 4];
                uint32_t a03 = St[(wmA + qr + 8 )*260 + kk + qc + 4];
                uint32_t a10 = St[(wmA + qr + 16)*260 + kk + qc];
                uint32_t a11 = St[(wmA + qr + 24)*260 + kk + qc];
                uint32_t a12 = St[(wmA + qr + 16)*260 + kk + qc + 4];
                uint32_t a13 = St[(wmA + qr + 24)*260 + kk + qc + 4];
#pragma unroll
                for (int j = 0; j < 4; j++) {
                    const int n = wnA + j*8 + qr;
                    uint32_t b0 = W1s[(kk + qc    )*72 + n];
                    uint32_t b1 = W1s[(kk + qc + 4)*72 + n];
                    mma8(acc[0][j], a00, a01, a02, a03, b0, b1);
                    mma8(acc[1][j], a10, a11, a12, a13, b0, b1);
                }
            }
            const float* hp = g_hpost + (size_t)t*BB*HH;
            const int mA = bmA*64 + wmA + qr;
#pragma unroll
            for (int h = 0; h < 2; h++) {
#pragma unroll
                for (int j = 0; j < 4; j++) {
                    const int n = bnA*64 + wnA + j*8 + qc*2;
                    const int r0 = mA + h*16, r1 = r0 + 8;
                    *(float2*)&zwt[(size_t)r0*HH + n] = make_float2(acc[h][j][0], acc[h][j][1]);
                    *(float2*)&zwt[(size_t)r1*HH + n] = make_float2(acc[h][j][2], acc[h][j][3]);
                    // hid = tf32(relu(zw + hpost)) — transformed ONCE here
                    float2 h0 = *(const float2*)&hp[(size_t)(r0 >> 3)*HH + n];
                    float2 h1 = *(const float2*)&hp[(size_t)(r1 >> 3)*HH + n];
                    uint2 u0, u1;
                    u0.x = f2tf(fmaxf(acc[h][j][0] + h0.x, 0.f));
                    u0.y = f2tf(fmaxf(acc[h][j][1] + h0.y, 0.f));
                    u1.x = f2tf(fmaxf(acc[h][j][2] + h1.x, 0.f));
                    u1.y = f2tf(fmaxf(acc[h][j][3] + h1.y, 0.f));
                    *(uint2*)&g_hid[(size_t)r0*HH + n] = u0;
                    *(uint2*)&g_hid[(size_t)r1*HH + n] = u1;
                }
            }
        }
        gbar(tgt, grp);

        // ============ phase B1: partial hid@W2 (tf32 mma, cp.async stage) ============
        {
#pragma unroll
            for (int i = 0; i < 32; i++) {
                int slot = tid + SCAN_THREADS * i;   // 0..4095
                int row = slot >> 6, qw = (slot & 63) << 2;
                cp16(stb + (uint32_t)(row*260 + qw) * 4,
                     &g_hid[(size_t)(moB*64 + row)*HH + kcB*256 + qw]);
            }
            CP_COMMIT(); CP_WAIT0();
            __syncthreads();

            float acc[2][4][4];
#pragma unroll
            for (int h = 0; h < 2; h++)
#pragma unroll
                for (int j = 0; j < 4; j++)
#pragma unroll
                    for (int c = 0; c < 4; c++) acc[h][j][c] = 0.f;

#pragma unroll 4
            for (int kb = 0; kb < 32; kb++) {
                const int kk = kb * 8;
                uint32_t a00 = St[(wrB + qr     )*260 + kk + qc];
                uint32_t a01 = St[(wrB + qr + 8 )*260 + kk + qc];
                uint32_t a02 = St[(wrB + qr     )*260 + kk + qc + 4];
                uint32_t a03 = St[(wrB + qr + 8 )*260 + kk + qc + 4];
                uint32_t a10 = St[(wrB + qr + 16)*260 + kk + qc];
                uint32_t a11 = St[(wrB + qr + 24)*260 + kk + qc];
                uint32_t a12 = St[(wrB + qr + 16)*260 + kk + qc + 4];
                uint32_t a13 = St[(wrB + qr + 24)*260 + kk + qc + 4];
#pragma unroll
                for (int j = 0; j < 4; j++) {
                    const int n = wcB + j*8 + qr;
                    uint32_t b0 = W2s[(kk + qc    )*72 + n];
                    uint32_t b1 = W2s[(kk + qc + 4)*72 + n];
                    mma8(acc[0][j], a00, a01, a02, a03, b0, b1);
                    mma8(acc[1][j], a10, a11, a12, a13, b0, b1);
                }
            }
            float* gp = g_part + (size_t)kcB*BSZ*ZZ;
            const int mB = moB*64 + wrB + qr;
#pragma unroll
            for (int h = 0; h < 2; h++) {
#pragma unroll
                for (int j = 0; j < 4; j++) {
                    const int n = noB*64 + wcB + j*8 + qc*2;
                    const int r0 = mB + h*16;
                    *(float2*)&gp[(size_t)r0*ZZ + n]     = make_float2(acc[h][j][0], acc[h][j][1]);
                    *(float2*)&gp[(size_t)(r0+8)*ZZ + n] = make_float2(acc[h][j][2], acc[h][j][3]);
                }
            }
        }
        gbar(tgt, grp);

        // ============ phase B2: combine + tanh + Euler + row minmax (fp32) ============
        {
            const int row = bid*4 + wid;
            const float* zr = g_states + (size_t)t*BSZ*ZZ + (size_t)row*ZZ;
            const float* nr = noise + (size_t)t*BSZ*ZZ + (size_t)row*ZZ;
            const float* dr = g_diff + ((size_t)t*BB + (row >> 3))*ZZ;
            float* pr = g_post + (size_t)t*BSZ*ZZ + (size_t)row*ZZ;
            float* outz = g_states + (size_t)(t+1)*BSZ*ZZ + (size_t)row*ZZ;
            float* outztf = g_states_tf + (size_t)(t+1)*BSZ*ZZ + (size_t)row*ZZ;

            float v8[8];
            float vmin = 3.4e38f, vmax = -3.4e38f;
#pragma unroll
            for (int j = 0; j < 2; j++) {
                const int cb = lane*4 + 128*j;
                float4 s  = *(const float4*)&g_part[0*BSZ*ZZ + (size_t)row*ZZ + cb];
                float4 s1 = *(const float4*)&g_part[1*BSZ*ZZ + (size_t)row*ZZ + cb];
                float4 s2 = *(const float4*)&g_part[2*BSZ*ZZ + (size_t)row*ZZ + cb];
                float4 s3 = *(const float4*)&g_part[3*BSZ*ZZ + (size_t)row*ZZ + cb];
                float4 bb = *(const float4*)&b2[cb];
                float4 zv = *(const float4*)&zr[cb];
                float4 nv = *(const float4*)&nr[cb];
                float4 dv = *(const float4*)&dr[cb];
                float pd0 = 0.1f * tanhf(s.x + s1.x + s2.x + s3.x + bb.x);
                float pd1 = 0.1f * tanhf(s.y + s1.y + s2.y + s3.y + bb.y);
                float pd2 = 0.1f * tanhf(s.z + s1.z + s2.z + s3.z + bb.z);
                float pd3 = 0.1f * tanhf(s.w + s1.w + s2.w + s3.w + bb.w);
                *(float4*)&pr[cb] = make_float4(pd0, pd1, pd2, pd3);
                float n0v = zv.x + DT_C*pd0 + SQRT_DT_C*dv.x*nv.x;
                float n1v = zv.y + DT_C*pd1 + SQRT_DT_C*dv.y*nv.y;
                float n2v = zv.z + DT_C*pd2 + SQRT_DT_C*dv.z*nv.z;
                float n3v = zv.w + DT_C*pd3 + SQRT_DT_C*dv.w*nv.w;
                v8[j*4+0] = n0v; v8[j*4+1] = n1v; v8[j*4+2] = n2v; v8[j*4+3] = n3v;
                vmin = fminf(vmin, fminf(fminf(n0v, n1v), fminf(n2v, n3v)));
                vmax = fmaxf(vmax, fmaxf(fmaxf(n0v, n1v), fmaxf(n2v, n3v)));
            }
#pragma unroll
            for (int o = 16; o > 0; o >>= 1) {
                vmin = fminf(vmin, __shfl_xor_sync(0xffffffffu, vmin, o));
                vmax = fmaxf(vmax, __shfl_xor_sync(0xffffffffu, vmax, o));
            }
            const float inv = 1.f / (vmax - vmin);
#pragma unroll
            for (int j = 0; j < 2; j++) {
                const int cb = lane*4 + 128*j;
                float z0v = (v8[j*4+0]-vmin)*inv, z1v = (v8[j*4+1]-vmin)*inv;
                float z2v = (v8[j*4+2]-vmin)*inv, z3v = (v8[j*4+3]-vmin)*inv;
                *(float4*)&outz[cb] = make_float4(z0v, z1v, z2v, z3v);
                uint4 u;
                u.x = f2tf(z0v); u.y = f2tf(z1v); u.z = f2tf(z2v); u.w = f2tf(z3v);
                *(uint4*)&outztf[cb] = u;
            }
        }
        gbar(tgt, grp);
    }
}

// ---------------- weight/activation tf32 pre-conversion (+barrier reset) --
__global__ void convw_kernel(const float* __restrict__ dw1,
                             const float* __restrict__ pw1,
                             const float* __restrict__ dif1,
                             const float* __restrict__ dif2,
                             const float* __restrict__ drw2,
                             const float* __restrict__ pw2,
                             const float* __restrict__ ph,
                             const float* __restrict__ php)
{
    if (blockIdx.x == 0 && threadIdx.x < 32) g_cnt[threadIdx.x << 5] = 0u;
    const long N1 = (long)(RR+ZZ)*HH;
    const long N3 = (long)RR*HH;
    const long N4 = (long)HH*ZZ;
    const long N5 = (long)HH*DD;
    const long N6 = (long)TT*BB*RR;
    const long total = 2*N1 + N3 + 2*N4 + N5 + 2*N6;
    for (long i = (long)blockIdx.x*blockDim.x + threadIdx.x; i < total;
         i += (long)gridDim.x*blockDim.x) {
        long j = i;
        if (j < N1) { g_w1tf[j]  = __uint_as_float(f2tf(dw1[j]));  continue; }
        j -= N1;
        if (j < N1) { g_pw1tf[j] = __uint_as_float(f2tf(pw1[j]));  continue; }
        j -= N1;
        if (j < N3) { g_dw1tf[j] = __uint_as_float(f2tf(dif1[j])); continue; }
        j -= N3;
        if (j < N4) { g_dfw2tf[j] = __uint_as_float(f2tf(dif2[j])); continue; }
        j -= N4;
        if (j < N4) { g_drw2tf[j] = __uint_as_float(f2tf(drw2[j])); continue; }
        j -= N4;
        if (j < N5) { g_pw2tf[j] = __uint_as_float(f2tf(pw2[j]));  continue; }
        j -= N5;
        if (j < N6) { g_phtf[j]  = __uint_as_float(f2tf(ph[j]));   continue; }
        j -= N6;
        g_hptf[j] = __uint_as_float(f2tf(php[j]));
    }
}

// ---------------- small kernels ----------------
__global__ void mt_kernel(const float* __restrict__ M)
{
    int r = blockIdx.x * blockDim.x + threadIdx.x;
    if (r < TT * BB) {
        const float* p = M + (size_t)r * DD;
        float s = 0.f;
        for (int d = 0; d < DD; d++) s += p[d];
        g_Mt[r] = s * (1.f / DD);
    }
}

__global__ void z0_kernel(const float* __restrict__ cov,
                          const float* __restrict__ w1, const float* __restrict__ b1,
                          const float* __restrict__ w2, const float* __restrict__ b2)
{
    int b = blockIdx.x;
    __shared__ float cv[16];
    __shared__ float hid[64];
    if (threadIdx.x < 16) cv[threadIdx.x] = cov[b * 16 + threadIdx.x];
    __syncthreads();
    if (threadIdx.x < 64) {
        float s = b1[threadIdx.x];
        for (int i = 0; i < 16; i++) s += cv[i] * w1[i * 64 + threadIdx.x];
        hid[threadIdx.x] = fmaxf(s, 0.f);
    }
    __syncthreads();
    int n = threadIdx.x;
    float s = b2[n];
    for (int j = 0; j < 64; j++) s += hid[j] * w2[j * 256 + n];
    float z = tanhf(s);
    for (int ss = 0; ss < SS; ss++) {
        g_states[(size_t)(b * SS + ss) * ZZ + n] = z;
        g_states_tf[(size_t)(b * SS + ss) * ZZ + n] = __uint_as_float(f2tf(z));
    }
}

__global__ void out_copy_kernel(float* __restrict__ out)
{
    int i = blockIdx.x * 256 + threadIdx.x;
    out[i] = g_states[(size_t)TT * BSZ * ZZ + i];
}

__global__ void scal_kernel(float* __restrict__ out)
{
    __shared__ float red[256];
    int tid = threadIdx.x;
    float s = 0.f;
    for (int i = tid; i < KLD_PARTS; i += 256) s += g_kld_part[i];
    red[tid] = s;
    __syncthreads();
    for (int o = 128; o > 0; o >>= 1) { if (tid < o) red[tid] += red[tid + o]; __syncthreads(); }
    float kldsum = red[0];
    __syncthreads();
    s = 0.f;
    for (int i = tid; i < RECON_PARTS; i += 256) s += g_recon_part[i];
    red[tid] = s;
    __syncthreads();
    for (int o = 128; o > 0; o >>= 1) { if (tid < o) red[tid] += red[tid + o]; __syncthreads(); }
    if (tid == 0) {
        float reconsum = red[0];
        float lk = (0.5f * DT_C / (float)(BB * SS)) * kldsum;
        float lr = reconsum * (1.f / (float)(BB * SS));
        out[131072] = lr + lk;   // loss_total
        out[131073] = lr;        // loss_recon
        out[131074] = lk;        // loss_kld
    }
}

// ---------------- launch ----------------
extern "C" void kernel_launch(void* const* d_in, const int* in_sizes, int n_in,
                              void* d_out, int out_size)
{
    (void)in_sizes; (void)n_in; (void)out_size;
    const float* X        = (const float*)d_in[0];
    const float* M        = (const float*)d_in[1];
    const float* cov      = (const float*)d_in[2];
    const float* path_h   = (const float*)d_in[3];
    const float* path_hpos= (const float*)d_in[4];
    const float* noise    = (const float*)d_in[5];
    const float* drift_w1 = (const float*)d_in[6];
    const float* drift_b1 = (const float*)d_in[7];
    const float* drift_w2 = (const float*)d_in[8];
    const float* drift_b2 = (const float*)d_in[9];
    const float* diff_w1  = (const float*)d_in[10];
    const float* diff_b1  = (const float*)d_in[11];
    const float* diff_w2  = (const float*)d_in[12];
    const float* diff_b2  = (const float*)d_in[13];
    const float* p_w1     = (const float*)d_in[14];
    const float* p_b1     = (const float*)d_in[15];
    const float* p_w2     = (const float*)d_in[16];
    const float* p_b2     = (const float*)d_in[17];
    const float* cov_w1   = (const float*)d_in[18];
    const float* cov_b1   = (const float*)d_in[19];
    const float* cov_w2   = (const float*)d_in[20];
    const float* cov_b2   = (const float*)d_in[21];
    float* out = (float*)d_out;

    float *hprior, *hpost, *ppart, *dtmp, *diffp, *states, *zw, *post, *A3, *kldp, *reconp, *Mtp;
    float *w1tf, *pw1tf, *dw1tf, *dfw2tf, *drw2tf, *pw2tf, *phtf, *hptf;
    cudaGetSymbolAddress((void**)&hprior, g_hprior);
    cudaGetSymbolAddress((void**)&hpost,  g_hpost);
    cudaGetSymbolAddress((void**)&ppart,  g_ppart);
    cudaGetSymbolAddress((void**)&dtmp,   g_dtmp);
    cudaGetSymbolAddress((void**)&diffp,  g_diff);
    cudaGetSymbolAddress((void**)&states, g_states);
    cudaGetSymbolAddress((void**)&zw,     g_zw);
    cudaGetSymbolAddress((void**)&post,   g_post);
    cudaGetSymbolAddress((void**)&A3,     g_A3);
    cudaGetSymbolAddress((void**)&kldp,   g_kld_part);
    cudaGetSymbolAddress((void**)&reconp, g_recon_part);
    cudaGetSymbolAddress((void**)&Mtp,    g_Mt);
    cudaGetSymbolAddress((void**)&w1tf,   g_w1tf);
    cudaGetSymbolAddress((void**)&pw1tf,  g_pw1tf);
    cudaGetSymbolAddress((void**)&dw1tf,  g_dw1tf);
    cudaGetSymbolAddress((void**)&dfw2tf, g_dfw2tf);
    cudaGetSymbolAddress((void**)&drw2tf, g_drw2tf);
    cudaGetSymbolAddress((void**)&pw2tf,  g_pw2tf);
    cudaGetSymbolAddress((void**)&phtf,   g_phtf);
    cudaGetSymbolAddress((void**)&hptf,   g_hptf);

    static int smem_set = 0;
    if (!smem_set) {
        cudaFuncSetAttribute(scan_kernel,
                             cudaFuncAttributeMaxDynamicSharedMemorySize, SMEM_SCAN);
        smem_set = 1;
    }

    // tf32 pre-conversion + barrier reset
    convw_kernel<<<4096, 256>>>(drift_w1, p_w1, diff_w1, diff_w2, drift_w2, p_w2,
                                path_h, path_hpos);
    // hpost (needed by scan)
    gemm_t<PRO_PLAIN, EPI_STORE, 1, 1, 0><<<dim3(16, 100), 256>>>(
        hptf, RR, w1tf, HH, hpost, HH, RR, drift_b1,
        nullptr, nullptr, nullptr, nullptr);
    // dtmp (tf32-rounded store)
    gemm_t<PRO_PLAIN, EPI_RELU, 1, 1, 1><<<dim3(16, 100), 256>>>(
        phtf, RR, dw1tf, HH, dtmp, HH, RR, diff_b1,
        nullptr, nullptr, nullptr, nullptr);
    // diffusion (needed by scan)
    gemm_t<PRO_PLAIN, EPI_EXP, 1, 1, 0><<<dim3(4, 100), 256>>>(
        dtmp, HH, dfw2tf, ZZ, diffp, ZZ, HH, diff_b2,
        nullptr, nullptr, nullptr, nullptr);
    // z0
    z0_kernel<<<BB, 256>>>(cov, cov_w1, cov_b1, cov_w2, cov_b2);
    // persistent scan (group-scoped barriers)
    scan_kernel<<<SCAN_BLOCKS, SCAN_THREADS, SMEM_SCAN>>>(
        w1tf + (size_t)RR * HH, drw2tf, drift_b2, noise);

    // batch epilogue
    gemm_t<PRO_PLAIN, EPI_STORE, 1, 1, 0><<<dim3(16, 100), 256>>>(
        phtf, RR, w1tf, HH, hprior, HH, RR, drift_b1,
        nullptr, nullptr, nullptr, nullptr);
    gemm_t<PRO_PLAIN, EPI_STORE, 1, 1, 0><<<dim3(16, 100), 256>>>(
        phtf, RR, pw1tf, HH, ppart, HH, RR, p_b1,
        nullptr, nullptr, nullptr, nullptr);
    mt_kernel<<<(TT * BB + 255) / 256, 256>>>(M);
    gemm_t<PRO_ADDRELU, EPI_KLD, 0, 0, 0><<<dim3(4, 800), 256>>>(
        zw, HH, drift_w2, ZZ, nullptr, 0, HH, drift_b2,
        hprior, post, diffp, kldp);
    gemm_t<PRO_PLAIN, EPI_BCASTRELU, 0, 1, 1><<<dim3(16, 800), 256>>>(
        states + (size_t)BSZ * ZZ, ZZ, pw1tf + (size_t)RR * HH, HH,
        A3, HH, ZZ, nullptr, ppart, nullptr, nullptr, nullptr);
    gemm_t<PRO_PLAIN, EPI_RECON, 1, 1, 0><<<dim3(2, 800), 256>>>(
        A3, HH, pw2tf, DD, nullptr, 0, HH, p_b2,
        X, Mtp, nullptr, reconp);

    // output: z_final then (total, recon, kld)
    out_copy_kernel<<<512, 256>>>(out);
    scal_kernel<<<1, 256>>>(out);
}